// round 12
// baseline (speedup 1.0000x reference)
#include <cuda_runtime.h>
#include <cuda_fp16.h>
#include <cstdint>

#define BSZ 2
#define NSEQ 2048
#define DIMM 256
#define HH 8
#define DHD 32
#define M_TOT (BSZ*NSEQ)
#define KK1 512
#define NN1 1536
#define NN2 512

// ---------------- scratch ------------------------------------------------------
__device__ __align__(16) __half g_Xh[M_TOT*KK1];
__device__ __align__(16) __half g_Xl[M_TOT*KK1];
__device__ __align__(16) __half g_W1th[NN1*KK1];
__device__ __align__(16) __half g_W1tl[NN1*KK1];
__device__ __align__(16) __half g_W2th[NN2*KK1];
__device__ __align__(16) __half g_W2tl[NN2*KK1];
__device__ __align__(16) __half g_Qrh[16*2048*32], g_Qrl[16*2048*32];
__device__ __align__(16) __half g_Qih[16*2048*32], g_Qil[16*2048*32];
__device__ __align__(16) __half g_Krh[16*2048*32], g_Krl[16*2048*32];
__device__ __align__(16) __half g_Kih[16*2048*32], g_Kil[16*2048*32];
__device__ __align__(16) __half g_VTh[16*64*2048];          // [bh][d(vr|vi)][n]
__device__ __align__(16) __half g_Mh[M_TOT*KK1];            // [4096][512] (Mr|Mi) hi
__device__ __align__(16) __half g_Ml[M_TOT*KK1];            // lo

// ---------------- PTX helpers --------------------------------------------------
__device__ __forceinline__ uint32_t smem_u32(const void* p) {
    uint32_t a;
    asm("{ .reg .u64 t; cvta.to.shared.u64 t, %1; cvt.u32.u64 %0, t; }" : "=r"(a) : "l"(p));
    return a;
}
__device__ __forceinline__ void cp16(uint32_t dst, const void* src) {
    asm volatile("cp.async.cg.shared.global [%0], [%1], 16;" :: "r"(dst), "l"(src));
}
#define CP_COMMIT() asm volatile("cp.async.commit_group;" ::: "memory")
#define CP_WAIT0()  asm volatile("cp.async.wait_group 0;" ::: "memory")

__device__ __forceinline__ void ldm4(uint32_t* r, uint32_t addr) {
    asm volatile("ldmatrix.sync.aligned.m8n8.x4.shared.b16 {%0,%1,%2,%3}, [%4];"
        : "=r"(r[0]), "=r"(r[1]), "=r"(r[2]), "=r"(r[3]) : "r"(addr));
}
__device__ __forceinline__ void mma16816(float* d, const uint32_t* a, const uint32_t* b) {
    asm volatile("mma.sync.aligned.m16n8k16.row.col.f32.f16.f16.f32 "
        "{%0,%1,%2,%3}, {%4,%5,%6,%7}, {%8,%9}, {%0,%1,%2,%3};"
        : "+f"(d[0]), "+f"(d[1]), "+f"(d[2]), "+f"(d[3])
        : "r"(a[0]), "r"(a[1]), "r"(a[2]), "r"(a[3]), "r"(b[0]), "r"(b[1]));
}
__device__ __forceinline__ uint32_t pk(float a, float b) {
    __half2 h = __floats2half2_rn(a, b);
    return *reinterpret_cast<uint32_t*>(&h);
}
__device__ __forceinline__ uint32_t ex2h2(uint32_t a) {
    uint32_t r; asm("ex2.approx.f16x2 %0, %1;" : "=r"(r) : "r"(a)); return r;
}

// ---------------- input / weight packing ----------------------------------------
__global__ void xsplit(const float* __restrict__ xr, const float* __restrict__ xi) {
    int idx = blockIdx.x*blockDim.x + threadIdx.x;
    if (idx >= M_TOT*KK1) return;
    int m = idx >> 9, k = idx & 511;
    float v = (k < 256) ? xr[m*256 + k] : xi[m*256 + k - 256];
    __half hi = __float2half_rn(v);
    g_Xh[idx] = hi;
    g_Xl[idx] = __float2half_rn(v - __half2float(hi));
}
__global__ void pack_w1t(const float* __restrict__ wq_r, const float* __restrict__ wq_i,
                         const float* __restrict__ wkv_r, const float* __restrict__ wkv_i) {
    int idx = blockIdx.x*blockDim.x + threadIdx.x;
    if (idx >= NN1*KK1) return;
    int c = idx >> 9, k = idx & 511;
    int reg = c >> 8, cc = c & 255;
    bool top = (k < 256);
    int kr = k & 255;
    float v;
    switch (reg) {
        case 0: v = top ? wq_r[kr*256+cc]      : -wq_i[kr*256+cc];      break;
        case 1: v = top ? wq_i[kr*256+cc]      :  wq_r[kr*256+cc];      break;
        case 2: v = top ? wkv_r[kr*512+cc]     : -wkv_i[kr*512+cc];     break;
        case 3: v = top ? wkv_i[kr*512+cc]     :  wkv_r[kr*512+cc];     break;
        case 4: v = top ? wkv_r[kr*512+256+cc] : -wkv_i[kr*512+256+cc]; break;
        default:v = top ? wkv_i[kr*512+256+cc] :  wkv_r[kr*512+256+cc]; break;
    }
    __half hi = __float2half_rn(v);
    g_W1th[idx] = hi;
    g_W1tl[idx] = __float2half_rn(v - __half2float(hi));
}
__global__ void pack_w2t(const float* __restrict__ wo_r, const float* __restrict__ wo_i) {
    int idx = blockIdx.x*blockDim.x + threadIdx.x;
    if (idx >= NN2*KK1) return;
    int c = idx >> 9, k = idx & 511;
    bool top = (k < 256);
    int kr = k & 255, co = c & 255;
    float v;
    if (c < 256) v = top ? wo_r[kr*256+co] : -wo_i[kr*256+co];
    else         v = top ? wo_i[kr*256+co] :  wo_r[kr*256+co];
    __half hi = __float2half_rn(v);
    g_W2th[idx] = hi;
    g_W2tl[idx] = __float2half_rn(v - __half2float(hi));
}

// ---------------- HMMA GEMM core, tile M=128 x N=64 (fp16 hi/lo 3-pass) ----------
// stage: Ah[128][40]h @0 (10240) | Al @10240 | Bh[64][40]h @20480 | Bl @25600 ; 30720/stage
#define GSTG 30720
#define GSM (2*GSTG)

// mainloop shared by both GEMMs; Xc[8][4] accumulators for a 16x64 strip per warp
__device__ __forceinline__ void gemm_core(const __half* Ah, const __half* Al,
                                          const __half* Bh, const __half* Bl,
                                          unsigned char* sm, int mBase, int nBase,
                                          float Xc[8][4]) {
    const int tid = threadIdx.x, w = tid >> 5, lane = tid & 31;
    const uint32_t smb = smem_u32(sm);
    const int r8 = lane & 7, q = lane >> 3;

    auto prefetch = [&](int t) {
        int k0 = t * 32;
        uint32_t so = smb + (uint32_t)(t & 1) * GSTG;
        #pragma unroll
        for (int i = 0; i < 2; i++) {
            int c = tid + (i << 8);
            int row = c >> 2, seg = c & 3;
            size_t ga = (size_t)(mBase + row)*512 + k0 + seg*8;
            cp16(so + row*80 + seg*16, Ah + ga);
            cp16(so + 10240 + row*80 + seg*16, Al + ga);
        }
        {
            int row = tid >> 2, seg = tid & 3;
            size_t gb = (size_t)(nBase + row)*512 + k0 + seg*8;
            cp16(so + 20480 + row*80 + seg*16, Bh + gb);
            cp16(so + 25600 + row*80 + seg*16, Bl + gb);
        }
    };

    prefetch(0); CP_COMMIT();
    CP_WAIT0();
    __syncthreads();

    for (int t = 0; t < 16; t++) {
        uint32_t so = smb + (uint32_t)(t & 1) * GSTG;
        if (t < 15) { prefetch(t + 1); CP_COMMIT(); }

        uint32_t ah[2][4], al[2][4];
        #pragma unroll
        for (int ks = 0; ks < 2; ks++) {
            uint32_t ad = so + (uint32_t)(16*w + r8 + (q & 1)*8)*80 + ks*32 + (q >> 1)*16;
            ldm4(ah[ks], ad);
            ldm4(al[ks], ad + 10240);
        }
        #pragma unroll
        for (int nbp = 0; nbp < 4; nbp++) {
            #pragma unroll
            for (int ks = 0; ks < 2; ks++) {
                uint32_t ad = so + 20480 + (uint32_t)(nbp*16 + r8 + (q >> 1)*8)*80 + ks*32 + (q & 1)*16;
                uint32_t bh4[4], bl4[4];
                ldm4(bh4, ad);
                ldm4(bl4, ad + 5120);
                mma16816(Xc[2*nbp],   ah[ks], bh4);
                mma16816(Xc[2*nbp+1], ah[ks], bh4+2);
                mma16816(Xc[2*nbp],   ah[ks], bl4);
                mma16816(Xc[2*nbp+1], ah[ks], bl4+2);
                mma16816(Xc[2*nbp],   al[ks], bh4);
                mma16816(Xc[2*nbp+1], al[ks], bh4+2);
            }
        }
        if (t < 15) { CP_WAIT0(); __syncthreads(); }
    }
}

__global__ void __launch_bounds__(256, 2) gemm1_mma() {
    extern __shared__ __align__(16) unsigned char sm[];
    const int w = threadIdx.x >> 5, lane = threadIdx.x & 31;
    const int mBase = blockIdx.y * 128, nBase = blockIdx.x * 64;
    float Xc[8][4] = {};
    gemm_core(g_Xh, g_Xl, g_W1th, g_W1tl, sm, mBase, nBase, Xc);

    #pragma unroll
    for (int nf = 0; nf < 8; nf++) {
        #pragma unroll
        for (int e = 0; e < 4; e++) {
            int m = mBase + 16*w + (e >> 1)*8 + (lane >> 2);
            int c = nBase + nf*8 + (lane & 3)*2 + (e & 1);
            float v = Xc[nf][e];
            int reg = c >> 8, rem = c & 255;
            int hd = rem >> 5, d = rem & 31;
            int b = m >> 11, n = m & 2047;
            int bhq = b*HH + hd;
            __half hi = __float2half_rn(v);
            if (reg < 4) {
                __half lo = __float2half_rn(v - __half2float(hi));
                size_t off = ((size_t)bhq*2048 + n)*32 + d;
                switch (reg) {
                    case 0: g_Qrh[off] = hi; g_Qrl[off] = lo; break;
                    case 1: g_Qih[off] = hi; g_Qil[off] = lo; break;
                    case 2: g_Krh[off] = hi; g_Krl[off] = lo; break;
                    default:g_Kih[off] = hi; g_Kil[off] = lo; break;
                }
            } else {
                g_VTh[((size_t)bhq*64 + (reg-4)*32 + d)*2048 + n] = hi;
            }
        }
    }
}

__global__ void __launch_bounds__(256, 2) gemm2_mma(float* __restrict__ outp) {
    extern __shared__ __align__(16) unsigned char sm[];
    const int w = threadIdx.x >> 5, lane = threadIdx.x & 31;
    const int mBase = blockIdx.y * 128, nBase = blockIdx.x * 64;
    float Xc[8][4] = {};
    gemm_core(g_Mh, g_Ml, g_W2th, g_W2tl, sm, mBase, nBase, Xc);

    #pragma unroll
    for (int nf = 0; nf < 8; nf++) {
        #pragma unroll
        for (int e = 0; e < 4; e++) {
            int m = mBase + 16*w + (e >> 1)*8 + (lane >> 2);
            int c = nBase + nf*8 + (lane & 3)*2 + (e & 1);
            outp[((size_t)m*DIMM + (c & 255))*2 + (c >> 8)] = Xc[nf][e];
        }
    }
}

// ---------------- HMMA attention --------------------------------------------------
#define SLOT 29696
#define SM_TOTAL (2*SLOT)

__global__ void __launch_bounds__(128, 2) attn_mma() {
    extern __shared__ __align__(16) unsigned char sm[];
    const int tid = threadIdx.x, w = tid >> 5, lane = tid & 31;
    const int bh = blockIdx.x;
    const int row0 = blockIdx.y * 32;
    const uint32_t smb = smem_u32(sm);
    const int r8 = lane & 7, q = lane >> 3;

    auto prefetch = [&](int t) {
        int ct = t * 64;
        uint32_t so = smb + (uint32_t)(t & 1) * SLOT;
        #pragma unroll
        for (int i = 0; i < 4; i++) {
            int c = tid + (i << 7);
            int row = c >> 2, pc = c & 3;
            size_t soff = ((size_t)bh*2048 + ct + (row & 63))*32 + pc*8;
            const __half* sh = (row < 64) ? g_Krh : g_Kih;
            const __half* sl = (row < 64) ? g_Krl : g_Kil;
            cp16(so + row*80 + pc*16, sh + soff);
            cp16(so + 10240 + row*80 + pc*16, sl + soff);
        }
        #pragma unroll
        for (int i = 0; i < 4; i++) {
            int c = tid + (i << 7);
            int dd = c >> 3, pc = c & 7;
            cp16(so + 20480 + dd*144 + pc*16,
                 g_VTh + ((size_t)bh*64 + dd)*2048 + ct + pc*8);
        }
    };

    prefetch(0); CP_COMMIT();

    const __half* Qh = (w < 2) ? g_Qrh : g_Qih;
    const __half* Ql = (w < 2) ? g_Qrl : g_Qil;
    size_t qoff = ((size_t)bh*2048 + row0 + (w & 1)*16 + (lane >> 2))*32 + (lane & 3)*2;
    uint32_t aqh[2][4], aql[2][4];
    #pragma unroll
    for (int ks = 0; ks < 2; ks++) {
        aqh[ks][0] = *(const uint32_t*)(Qh + qoff + ks*16);
        aqh[ks][1] = *(const uint32_t*)(Qh + qoff + 256 + ks*16);
        aqh[ks][2] = *(const uint32_t*)(Qh + qoff + ks*16 + 8);
        aqh[ks][3] = *(const uint32_t*)(Qh + qoff + 256 + ks*16 + 8);
        aql[ks][0] = *(const uint32_t*)(Ql + qoff + ks*16);
        aql[ks][1] = *(const uint32_t*)(Ql + qoff + 256 + ks*16);
        aql[ks][2] = *(const uint32_t*)(Ql + qoff + ks*16 + 8);
        aql[ks][3] = *(const uint32_t*)(Ql + qoff + 256 + ks*16 + 8);
    }
    CP_WAIT0();
    __syncthreads();

    float X[8][4] = {};
    float Y[8][4] = {};
    float l00 = 0.f, l01 = 0.f, l10 = 0.f, l11 = 0.f;
    const float C = (float)(1.4426950408889634 / 5.656854249492380);
    const float SHIFT = 10.0f;

    for (int t = 0; t < 32; t++) {
        uint32_t so = smb + (uint32_t)(t & 1) * SLOT;
        if (t < 31) { prefetch(t + 1); CP_COMMIT(); }

        float S[16][4];
        #pragma unroll
        for (int nb = 0; nb < 16; nb++)
            #pragma unroll
            for (int e = 0; e < 4; e++) S[nb][e] = 0.f;

        #pragma unroll
        for (int nbp = 0; nbp < 8; nbp++) {
            #pragma unroll
            for (int ks = 0; ks < 2; ks++) {
                uint32_t ad = so + (uint32_t)(nbp*16 + r8 + (q >> 1)*8)*80 + ks*32 + (q & 1)*16;
                uint32_t bh4[4], bl4[4];
                ldm4(bh4, ad);
                ldm4(bl4, ad + 10240);
                mma16816(S[2*nbp],   aqh[ks], bh4);
                mma16816(S[2*nbp+1], aqh[ks], bh4+2);
                mma16816(S[2*nbp],   aqh[ks], bl4);
                mma16816(S[2*nbp+1], aqh[ks], bl4+2);
                mma16816(S[2*nbp],   aql[ks], bh4);
                mma16816(S[2*nbp+1], aql[ks], bh4+2);
            }
        }

        // exp (f16x2) + PV per column-half: PV(h0) tensor work overlaps exp(h1) MUFU work
        uint32_t vt = so + 20480;
        #pragma unroll
        for (int h2 = 0; h2 < 2; h2++) {
            uint32_t Pf[4][4];
            float ls0 = 0.f, ls1 = 0.f;
            #pragma unroll
            for (int ks = 0; ks < 4; ks++) {
                int nb = 8*h2 + 2*ks;
                Pf[ks][0] = ex2h2(pk(fmaf(S[nb][0],   C, -SHIFT), fmaf(S[nb][1],   C, -SHIFT)));
                Pf[ks][1] = ex2h2(pk(fmaf(S[nb][2],   C, -SHIFT), fmaf(S[nb][3],   C, -SHIFT)));
                Pf[ks][2] = ex2h2(pk(fmaf(S[nb+1][0], C, -SHIFT), fmaf(S[nb+1][1], C, -SHIFT)));
                Pf[ks][3] = ex2h2(pk(fmaf(S[nb+1][2], C, -SHIFT), fmaf(S[nb+1][3], C, -SHIFT)));
                float2 f0 = __half22float2(*reinterpret_cast<__half2*>(&Pf[ks][0]));
                float2 f1 = __half22float2(*reinterpret_cast<__half2*>(&Pf[ks][1]));
                float2 f2 = __half22float2(*reinterpret_cast<__half2*>(&Pf[ks][2]));
                float2 f3 = __half22float2(*reinterpret_cast<__half2*>(&Pf[ks][3]));
                ls0 += f0.x + f0.y + f2.x + f2.y;
                ls1 += f1.x + f1.y + f3.x + f3.y;
            }
            if (h2 == 0) { l00 += ls0; l10 += ls1; }
            else         { l01 += ls0; l11 += ls1; }

            float (*Z)[4] = h2 ? Y : X;
            #pragma unroll
            for (int dbp = 0; dbp < 4; dbp++) {
                #pragma unroll
                for (int ks = 0; ks < 4; ks++) {
                    uint32_t ad = vt + (uint32_t)(dbp*16 + r8 + (q >> 1)*8)*144 + ks*32 + (q & 1)*16;
                    uint32_t bv[4];
                    ldm4(bv, ad);
                    mma16816(Z[2*dbp],   Pf[ks], bv);
                    mma16816(Z[2*dbp+1], Pf[ks], bv+2);
                }
            }
        }

        if (t < 31) { CP_WAIT0(); __syncthreads(); }
    }
    __syncthreads();

    l00 += __shfl_xor_sync(~0u, l00, 1); l00 += __shfl_xor_sync(~0u, l00, 2);
    l01 += __shfl_xor_sync(~0u, l01, 1); l01 += __shfl_xor_sync(~0u, l01, 2);
    l10 += __shfl_xor_sync(~0u, l10, 1); l10 += __shfl_xor_sync(~0u, l10, 2);
    l11 += __shfl_xor_sync(~0u, l11, 1); l11 += __shfl_xor_sync(~0u, l11, 2);
    float rl[2][2] = {{1.f/l00, 1.f/l01}, {1.f/l10, 1.f/l11}};

    float* orS = (float*)sm;             // [2][32][32]
    float* oiS = (float*)(sm + 8192);
    int grp = w >> 1;
    int mb = 16*(w & 1) + (lane >> 2);
    int dq = 2*(lane & 3);
    #pragma unroll
    for (int db = 0; db < 4; db++) {
        #pragma unroll
        for (int rr = 0; rr < 2; rr++) {
            #pragma unroll
            for (int dd = 0; dd < 2; dd++) {
                float x  = X[db][2*rr+dd]   * rl[rr][0];
                float x2 = X[db+4][2*rr+dd] * rl[rr][0];
                float y  = Y[db][2*rr+dd]   * rl[rr][1];
                float y2 = Y[db+4][2*rr+dd] * rl[rr][1];
                float orv = grp ? (-x2 - y) : (x - y2);
                float oiv = grp ? (x - y2)  : (x2 + y);
                int m = mb + rr*8, dcol = 8*db + dq + dd;
                orS[grp*1024 + m*32 + dcol] = orv;
                oiS[grp*1024 + m*32 + dcol] = oiv;
            }
        }
    }
    __syncthreads();
    {
        int b = bh >> 3, hh = bh & 7;
        for (int e = tid; e < 1024; e += 128) {
            int m = e >> 5, dcol = e & 31;
            float r  = orS[m*32 + dcol] + orS[1024 + m*32 + dcol];
            float im = oiS[m*32 + dcol] + oiS[1024 + m*32 + dcol];
            size_t o = ((size_t)(b*2048 + row0 + m))*512 + hh*32 + dcol;
            __half rh = __float2half_rn(r);
            __half ih = __float2half_rn(im);
            g_Mh[o]       = rh;
            g_Ml[o]       = __float2half_rn(r - __half2float(rh));
            g_Mh[o + 256] = ih;
            g_Ml[o + 256] = __float2half_rn(im - __half2float(ih));
        }
    }
}

// ---------------- launch -------------------------------------------------------------
extern "C" void kernel_launch(void* const* d_in, const int* in_sizes, int n_in,
                              void* d_out, int out_size) {
    const float* xr    = (const float*)d_in[0];
    const float* xi    = (const float*)d_in[1];
    const float* wq_r  = (const float*)d_in[2];
    const float* wq_i  = (const float*)d_in[3];
    const float* wkv_r = (const float*)d_in[4];
    const float* wkv_i = (const float*)d_in[5];
    const float* wo_r  = (const float*)d_in[6];
    const float* wo_i  = (const float*)d_in[7];
    float* out = (float*)d_out;

    cudaFuncSetAttribute(attn_mma,  cudaFuncAttributeMaxDynamicSharedMemorySize, SM_TOTAL);
    cudaFuncSetAttribute(gemm1_mma, cudaFuncAttributeMaxDynamicSharedMemorySize, GSM);
    cudaFuncSetAttribute(gemm2_mma, cudaFuncAttributeMaxDynamicSharedMemorySize, GSM);

    xsplit<<<(M_TOT*KK1 + 255)/256, 256>>>(xr, xi);
    pack_w1t<<<(NN1*KK1 + 255)/256, 256>>>(wq_r, wq_i, wkv_r, wkv_i);
    pack_w2t<<<(NN2*KK1 + 255)/256, 256>>>(wo_r, wo_i);
    gemm1_mma<<<dim3(NN1/64, M_TOT/128), 256, GSM>>>();
    attn_mma<<<dim3(16, 64), 128, SM_TOTAL>>>();
    gemm2_mma<<<dim3(NN2/64, M_TOT/128), 256, GSM>>>(out);
}

// round 13
// speedup vs baseline: 1.0541x; 1.0541x over previous
#include <cuda_runtime.h>
#include <cuda_fp16.h>
#include <cstdint>

#define BSZ 2
#define NSEQ 2048
#define DIMM 256
#define HH 8
#define DHD 32
#define M_TOT (BSZ*NSEQ)
#define KK1 512
#define NN1 1536
#define NN2 512

// ---------------- scratch ------------------------------------------------------
__device__ __align__(16) __half g_Xh[M_TOT*KK1];
__device__ __align__(16) __half g_W1th[NN1*KK1];
__device__ __align__(16) __half g_W1tl[NN1*KK1];
__device__ __align__(16) __half g_W2th[NN2*KK1];
__device__ __align__(16) __half g_W2tl[NN2*KK1];
__device__ __align__(16) __half g_Qrh[16*2048*32];
__device__ __align__(16) __half g_Qih[16*2048*32];
__device__ __align__(16) __half g_Krh[16*2048*32], g_Krl[16*2048*32];
__device__ __align__(16) __half g_Kih[16*2048*32], g_Kil[16*2048*32];
__device__ __align__(16) __half g_VTh[16*64*2048];          // [bh][d(vr|vi)][n]
__device__ __align__(16) __half g_Mh[M_TOT*KK1];            // [4096][512] (Mr|Mi) hi
__device__ __align__(16) __half g_Ml[M_TOT*KK1];            // lo

// ---------------- PTX helpers --------------------------------------------------
__device__ __forceinline__ uint32_t smem_u32(const void* p) {
    uint32_t a;
    asm("{ .reg .u64 t; cvta.to.shared.u64 t, %1; cvt.u32.u64 %0, t; }" : "=r"(a) : "l"(p));
    return a;
}
__device__ __forceinline__ void cp16(uint32_t dst, const void* src) {
    asm volatile("cp.async.cg.shared.global [%0], [%1], 16;" :: "r"(dst), "l"(src));
}
#define CP_COMMIT() asm volatile("cp.async.commit_group;" ::: "memory")
#define CP_WAIT0()  asm volatile("cp.async.wait_group 0;" ::: "memory")

__device__ __forceinline__ void ldm4(uint32_t* r, uint32_t addr) {
    asm volatile("ldmatrix.sync.aligned.m8n8.x4.shared.b16 {%0,%1,%2,%3}, [%4];"
        : "=r"(r[0]), "=r"(r[1]), "=r"(r[2]), "=r"(r[3]) : "r"(addr));
}
__device__ __forceinline__ void mma16816(float* d, const uint32_t* a, const uint32_t* b) {
    asm volatile("mma.sync.aligned.m16n8k16.row.col.f32.f16.f16.f32 "
        "{%0,%1,%2,%3}, {%4,%5,%6,%7}, {%8,%9}, {%0,%1,%2,%3};"
        : "+f"(d[0]), "+f"(d[1]), "+f"(d[2]), "+f"(d[3])
        : "r"(a[0]), "r"(a[1]), "r"(a[2]), "r"(a[3]), "r"(b[0]), "r"(b[1]));
}
__device__ __forceinline__ float ex2(float x) {
    float r; asm("ex2.approx.f32 %0, %1;" : "=f"(r) : "f"(x)); return r;
}
__device__ __forceinline__ uint32_t pk(float a, float b) {
    __half2 h = __floats2half2_rn(a, b);
    return *reinterpret_cast<uint32_t*>(&h);
}

// ---------------- input / weight packing ----------------------------------------
__global__ void xsplit(const float* __restrict__ xr, const float* __restrict__ xi) {
    int idx = blockIdx.x*blockDim.x + threadIdx.x;
    if (idx >= M_TOT*KK1) return;
    int m = idx >> 9, k = idx & 511;
    float v = (k < 256) ? xr[m*256 + k] : xi[m*256 + k - 256];
    g_Xh[idx] = __float2half_rn(v);
}
__global__ void pack_w1t(const float* __restrict__ wq_r, const float* __restrict__ wq_i,
                         const float* __restrict__ wkv_r, const float* __restrict__ wkv_i) {
    int idx = blockIdx.x*blockDim.x + threadIdx.x;
    if (idx >= NN1*KK1) return;
    int c = idx >> 9, k = idx & 511;
    int reg = c >> 8, cc = c & 255;
    bool top = (k < 256);
    int kr = k & 255;
    float v;
    switch (reg) {
        case 0: v = top ? wq_r[kr*256+cc]      : -wq_i[kr*256+cc];      break;
        case 1: v = top ? wq_i[kr*256+cc]      :  wq_r[kr*256+cc];      break;
        case 2: v = top ? wkv_r[kr*512+cc]     : -wkv_i[kr*512+cc];     break;
        case 3: v = top ? wkv_i[kr*512+cc]     :  wkv_r[kr*512+cc];     break;
        case 4: v = top ? wkv_r[kr*512+256+cc] : -wkv_i[kr*512+256+cc]; break;
        default:v = top ? wkv_i[kr*512+256+cc] :  wkv_r[kr*512+256+cc]; break;
    }
    __half hi = __float2half_rn(v);
    g_W1th[idx] = hi;
    g_W1tl[idx] = __float2half_rn(v - __half2float(hi));
}
__global__ void pack_w2t(const float* __restrict__ wo_r, const float* __restrict__ wo_i) {
    int idx = blockIdx.x*blockDim.x + threadIdx.x;
    if (idx >= NN2*KK1) return;
    int c = idx >> 9, k = idx & 511;
    bool top = (k < 256);
    int kr = k & 255, co = c & 255;
    float v;
    if (c < 256) v = top ? wo_r[kr*256+co] : -wo_i[kr*256+co];
    else         v = top ? wo_i[kr*256+co] :  wo_r[kr*256+co];
    __half hi = __float2half_rn(v);
    g_W2th[idx] = hi;
    g_W2tl[idx] = __float2half_rn(v - __half2float(hi));
}

// ---------------- GEMM1: 2-pass  Xh @ (W1h + W1l), tile 64x64 -------------------
// stage: Ah[64][40]h @0 (5120) | Bh @5120 | Bl @10240 ; 15360/stage, 30720 total
#define G1STG 15360

__global__ void __launch_bounds__(256, 2) gemm1_mma() {
    __shared__ __align__(16) unsigned char sm[2*G1STG];
    const int tid = threadIdx.x, w = tid >> 5, lane = tid & 31;
    const int wm = w & 3, wn = w >> 2;
    const int mBase = blockIdx.y * 64, nBase = blockIdx.x * 64;
    const uint32_t smb = smem_u32(sm);
    const int r8 = lane & 7, q = lane >> 3;

    auto prefetch = [&](int t) {
        int k0 = t * 32;
        uint32_t so = smb + (uint32_t)(t & 1) * G1STG;
        int row = tid >> 2, seg = tid & 3;
        size_t ga = (size_t)(mBase + row)*512 + k0 + seg*8;
        cp16(so + row*80 + seg*16, g_Xh + ga);
        size_t gb = (size_t)(nBase + row)*512 + k0 + seg*8;
        cp16(so + 5120 + row*80 + seg*16, g_W1th + gb);
        cp16(so + 10240 + row*80 + seg*16, g_W1tl + gb);
    };

    prefetch(0); CP_COMMIT();
    CP_WAIT0();
    __syncthreads();

    float Xc[4][4] = {};

    for (int t = 0; t < 16; t++) {
        uint32_t so = smb + (uint32_t)(t & 1) * G1STG;
        if (t < 15) { prefetch(t + 1); CP_COMMIT(); }

        uint32_t ah[2][4];
        #pragma unroll
        for (int ks = 0; ks < 2; ks++) {
            uint32_t ad = so + (uint32_t)(16*wm + r8 + (q & 1)*8)*80 + ks*32 + (q >> 1)*16;
            ldm4(ah[ks], ad);
        }
        #pragma unroll
        for (int nbp = 0; nbp < 2; nbp++) {
            #pragma unroll
            for (int ks = 0; ks < 2; ks++) {
                uint32_t ad = so + 5120
                            + (uint32_t)(wn*32 + nbp*16 + r8 + (q >> 1)*8)*80 + ks*32 + (q & 1)*16;
                uint32_t bh4[4], bl4[4];
                ldm4(bh4, ad);
                ldm4(bl4, ad + 5120);
                mma16816(Xc[2*nbp],   ah[ks], bh4);
                mma16816(Xc[2*nbp+1], ah[ks], bh4+2);
                mma16816(Xc[2*nbp],   ah[ks], bl4);
                mma16816(Xc[2*nbp+1], ah[ks], bl4+2);
            }
        }
        if (t < 15) { CP_WAIT0(); __syncthreads(); }
    }

    // ---- epilogue: Q hi only; K hi+lo; V transposed hi ----
    #pragma unroll
    for (int nf = 0; nf < 4; nf++) {
        #pragma unroll
        for (int e = 0; e < 4; e++) {
            int m = mBase + 16*wm + (e >> 1)*8 + (lane >> 2);
            int c = nBase + wn*32 + nf*8 + (lane & 3)*2 + (e & 1);
            float v = Xc[nf][e];
            int reg = c >> 8, rem = c & 255;
            int hd = rem >> 5, d = rem & 31;
            int b = m >> 11, n = m & 2047;
            int bhq = b*HH + hd;
            __half hi = __float2half_rn(v);
            size_t off = ((size_t)bhq*2048 + n)*32 + d;
            switch (reg) {
                case 0: g_Qrh[off] = hi; break;
                case 1: g_Qih[off] = hi; break;
                case 2: g_Krh[off] = hi; g_Krl[off] = __float2half_rn(v - __half2float(hi)); break;
                case 3: g_Kih[off] = hi; g_Kil[off] = __float2half_rn(v - __half2float(hi)); break;
                default:
                    g_VTh[((size_t)bhq*64 + (reg-4)*32 + d)*2048 + n] = hi;
            }
        }
    }
}

// ---------------- GEMM2: 3-pass (Mh/Ml) @ (W2h/W2l), tile 64x64 ------------------
#define G2STG 20480

__global__ void __launch_bounds__(256, 2) gemm2_mma(float* __restrict__ outp) {
    __shared__ __align__(16) unsigned char sm[2*G2STG];
    const int tid = threadIdx.x, w = tid >> 5, lane = tid & 31;
    const int wm = w & 3, wn = w >> 2;
    const int mBase = blockIdx.y * 64, nBase = blockIdx.x * 64;
    const uint32_t smb = smem_u32(sm);
    const int r8 = lane & 7, q = lane >> 3;

    auto prefetch = [&](int t) {
        int k0 = t * 32;
        uint32_t so = smb + (uint32_t)(t & 1) * G2STG;
        int row = tid >> 2, seg = tid & 3;
        size_t ga = (size_t)(mBase + row)*512 + k0 + seg*8;
        cp16(so + row*80 + seg*16, g_Mh + ga);
        cp16(so + 5120 + row*80 + seg*16, g_Ml + ga);
        size_t gb = (size_t)(nBase + row)*512 + k0 + seg*8;
        cp16(so + 10240 + row*80 + seg*16, g_W2th + gb);
        cp16(so + 15360 + row*80 + seg*16, g_W2tl + gb);
    };

    prefetch(0); CP_COMMIT();
    CP_WAIT0();
    __syncthreads();

    float Xc[4][4] = {};

    for (int t = 0; t < 16; t++) {
        uint32_t so = smb + (uint32_t)(t & 1) * G2STG;
        if (t < 15) { prefetch(t + 1); CP_COMMIT(); }

        uint32_t ah[2][4], al[2][4];
        #pragma unroll
        for (int ks = 0; ks < 2; ks++) {
            uint32_t ad = so + (uint32_t)(16*wm + r8 + (q & 1)*8)*80 + ks*32 + (q >> 1)*16;
            ldm4(ah[ks], ad);
            ldm4(al[ks], ad + 5120);
        }
        #pragma unroll
        for (int nbp = 0; nbp < 2; nbp++) {
            #pragma unroll
            for (int ks = 0; ks < 2; ks++) {
                uint32_t ad = so + 10240
                            + (uint32_t)(wn*32 + nbp*16 + r8 + (q >> 1)*8)*80 + ks*32 + (q & 1)*16;
                uint32_t bh4[4], bl4[4];
                ldm4(bh4, ad);
                ldm4(bl4, ad + 5120);
                mma16816(Xc[2*nbp],   ah[ks], bh4);
                mma16816(Xc[2*nbp+1], ah[ks], bh4+2);
                mma16816(Xc[2*nbp],   ah[ks], bl4);
                mma16816(Xc[2*nbp+1], ah[ks], bl4+2);
                mma16816(Xc[2*nbp],   al[ks], bh4);
                mma16816(Xc[2*nbp+1], al[ks], bh4+2);
            }
        }
        if (t < 15) { CP_WAIT0(); __syncthreads(); }
    }

    #pragma unroll
    for (int nf = 0; nf < 4; nf++) {
        #pragma unroll
        for (int e = 0; e < 4; e++) {
            int m = mBase + 16*wm + (e >> 1)*8 + (lane >> 2);
            int c = nBase + wn*32 + nf*8 + (lane & 3)*2 + (e & 1);
            outp[((size_t)m*DIMM + (c & 255))*2 + (c >> 8)] = Xc[nf][e];
        }
    }
}

// ---------------- HMMA attention (QK 2-pass, fp32 exp, interleaved PV) ----------
#define SLOT 29696
#define SM_TOTAL (2*SLOT)

__global__ void __launch_bounds__(128, 2) attn_mma() {
    extern __shared__ __align__(16) unsigned char sm[];
    const int tid = threadIdx.x, w = tid >> 5, lane = tid & 31;
    const int bh = blockIdx.x;
    const int row0 = blockIdx.y * 32;
    const uint32_t smb = smem_u32(sm);
    const int r8 = lane & 7, q = lane >> 3;

    auto prefetch = [&](int t) {
        int ct = t * 64;
        uint32_t so = smb + (uint32_t)(t & 1) * SLOT;
        #pragma unroll
        for (int i = 0; i < 4; i++) {
            int c = tid + (i << 7);
            int row = c >> 2, pc = c & 3;
            size_t soff = ((size_t)bh*2048 + ct + (row & 63))*32 + pc*8;
            const __half* sh = (row < 64) ? g_Krh : g_Kih;
            const __half* sl = (row < 64) ? g_Krl : g_Kil;
            cp16(so + row*80 + pc*16, sh + soff);
            cp16(so + 10240 + row*80 + pc*16, sl + soff);
        }
        #pragma unroll
        for (int i = 0; i < 4; i++) {
            int c = tid + (i << 7);
            int dd = c >> 3, pc = c & 7;
            cp16(so + 20480 + dd*144 + pc*16,
                 g_VTh + ((size_t)bh*64 + dd)*2048 + ct + pc*8);
        }
    };

    prefetch(0); CP_COMMIT();

    const __half* Qh = (w < 2) ? g_Qrh : g_Qih;
    size_t qoff = ((size_t)bh*2048 + row0 + (w & 1)*16 + (lane >> 2))*32 + (lane & 3)*2;
    uint32_t aqh[2][4];
    #pragma unroll
    for (int ks = 0; ks < 2; ks++) {
        aqh[ks][0] = *(const uint32_t*)(Qh + qoff + ks*16);
        aqh[ks][1] = *(const uint32_t*)(Qh + qoff + 256 + ks*16);
        aqh[ks][2] = *(const uint32_t*)(Qh + qoff + ks*16 + 8);
        aqh[ks][3] = *(const uint32_t*)(Qh + qoff + 256 + ks*16 + 8);
    }
    CP_WAIT0();
    __syncthreads();

    float X[8][4] = {};
    float Y[8][4] = {};
    float l00 = 0.f, l01 = 0.f, l10 = 0.f, l11 = 0.f;
    const float C = (float)(1.4426950408889634 / 5.656854249492380);
    const float SHIFT = 10.0f;

    for (int t = 0; t < 32; t++) {
        uint32_t so = smb + (uint32_t)(t & 1) * SLOT;
        if (t < 31) { prefetch(t + 1); CP_COMMIT(); }

        float S[16][4];
        #pragma unroll
        for (int nb = 0; nb < 16; nb++)
            #pragma unroll
            for (int e = 0; e < 4; e++) S[nb][e] = 0.f;

        // ---- S = Qh (Kh + Kl)^T : 2-pass ----
        #pragma unroll
        for (int nbp = 0; nbp < 8; nbp++) {
            #pragma unroll
            for (int ks = 0; ks < 2; ks++) {
                uint32_t ad = so + (uint32_t)(nbp*16 + r8 + (q >> 1)*8)*80 + ks*32 + (q & 1)*16;
                uint32_t bh4[4], bl4[4];
                ldm4(bh4, ad);
                ldm4(bl4, ad + 10240);
                mma16816(S[2*nbp],   aqh[ks], bh4);
                mma16816(S[2*nbp+1], aqh[ks], bh4+2);
                mma16816(S[2*nbp],   aqh[ks], bl4);
                mma16816(S[2*nbp+1], aqh[ks], bl4+2);
            }
        }

        // exp + PV per column-half (PV(h0) overlaps exp(h1))
        uint32_t vt = so + 20480;
        #pragma unroll
        for (int h2 = 0; h2 < 2; h2++) {
            uint32_t Pf[4][4];
            float ls0 = 0.f, ls1 = 0.f;
            #pragma unroll
            for (int ks = 0; ks < 4; ks++) {
                int nb = 8*h2 + 2*ks;
                float p00 = ex2(fmaf(S[nb][0],   C, -SHIFT));
                float p01 = ex2(fmaf(S[nb][1],   C, -SHIFT));
                float p02 = ex2(fmaf(S[nb][2],   C, -SHIFT));
                float p03 = ex2(fmaf(S[nb][3],   C, -SHIFT));
                float p10 = ex2(fmaf(S[nb+1][0], C, -SHIFT));
                float p11 = ex2(fmaf(S[nb+1][1], C, -SHIFT));
                float p12 = ex2(fmaf(S[nb+1][2], C, -SHIFT));
                float p13 = ex2(fmaf(S[nb+1][3], C, -SHIFT));
                ls0 += p00 + p01 + p10 + p11;
                ls1 += p02 + p03 + p12 + p13;
                Pf[ks][0] = pk(p00, p01);
                Pf[ks][1] = pk(p02, p03);
                Pf[ks][2] = pk(p10, p11);
                Pf[ks][3] = pk(p12, p13);
            }
            if (h2 == 0) { l00 += ls0; l10 += ls1; }
            else         { l01 += ls0; l11 += ls1; }

            float (*Z)[4] = h2 ? Y : X;
            #pragma unroll
            for (int dbp = 0; dbp < 4; dbp++) {
                #pragma unroll
                for (int ks = 0; ks < 4; ks++) {
                    uint32_t ad = vt + (uint32_t)(dbp*16 + r8 + (q >> 1)*8)*144 + ks*32 + (q & 1)*16;
                    uint32_t bv[4];
                    ldm4(bv, ad);
                    mma16816(Z[2*dbp],   Pf[ks], bv);
                    mma16816(Z[2*dbp+1], Pf[ks], bv+2);
                }
            }
        }

        if (t < 31) { CP_WAIT0(); __syncthreads(); }
    }
    __syncthreads();

    l00 += __shfl_xor_sync(~0u, l00, 1); l00 += __shfl_xor_sync(~0u, l00, 2);
    l01 += __shfl_xor_sync(~0u, l01, 1); l01 += __shfl_xor_sync(~0u, l01, 2);
    l10 += __shfl_xor_sync(~0u, l10, 1); l10 += __shfl_xor_sync(~0u, l10, 2);
    l11 += __shfl_xor_sync(~0u, l11, 1); l11 += __shfl_xor_sync(~0u, l11, 2);
    float rl[2][2] = {{1.f/l00, 1.f/l01}, {1.f/l10, 1.f/l11}};

    float* orS = (float*)sm;             // [2][32][32]
    float* oiS = (float*)(sm + 8192);
    int grp = w >> 1;
    int mb = 16*(w & 1) + (lane >> 2);
    int dq = 2*(lane & 3);
    #pragma unroll
    for (int db = 0; db < 4; db++) {
        #pragma unroll
        for (int rr = 0; rr < 2; rr++) {
            #pragma unroll
            for (int dd = 0; dd < 2; dd++) {
                float x  = X[db][2*rr+dd]   * rl[rr][0];
                float x2 = X[db+4][2*rr+dd] * rl[rr][0];
                float y  = Y[db][2*rr+dd]   * rl[rr][1];
                float y2 = Y[db+4][2*rr+dd] * rl[rr][1];
                float orv = grp ? (-x2 - y) : (x - y2);
                float oiv = grp ? (x - y2)  : (x2 + y);
                int m = mb + rr*8, dcol = 8*db + dq + dd;
                orS[grp*1024 + m*32 + dcol] = orv;
                oiS[grp*1024 + m*32 + dcol] = oiv;
            }
        }
    }
    __syncthreads();
    {
        int b = bh >> 3, hh = bh & 7;
        for (int e = tid; e < 1024; e += 128) {
            int m = e >> 5, dcol = e & 31;
            float r  = orS[m*32 + dcol] + orS[1024 + m*32 + dcol];
            float im = oiS[m*32 + dcol] + oiS[1024 + m*32 + dcol];
            size_t o = ((size_t)(b*2048 + row0 + m))*512 + hh*32 + dcol;
            __half rh = __float2half_rn(r);
            __half ih = __float2half_rn(im);
            g_Mh[o]       = rh;
            g_Ml[o]       = __float2half_rn(r - __half2float(rh));
            g_Mh[o + 256] = ih;
            g_Ml[o + 256] = __float2half_rn(im - __half2float(ih));
        }
    }
}

// ---------------- launch -------------------------------------------------------------
extern "C" void kernel_launch(void* const* d_in, const int* in_sizes, int n_in,
                              void* d_out, int out_size) {
    const float* xr    = (const float*)d_in[0];
    const float* xi    = (const float*)d_in[1];
    const float* wq_r  = (const float*)d_in[2];
    const float* wq_i  = (const float*)d_in[3];
    const float* wkv_r = (const float*)d_in[4];
    const float* wkv_i = (const float*)d_in[5];
    const float* wo_r  = (const float*)d_in[6];
    const float* wo_i  = (const float*)d_in[7];
    float* out = (float*)d_out;

    cudaFuncSetAttribute(attn_mma, cudaFuncAttributeMaxDynamicSharedMemorySize, SM_TOTAL);

    xsplit<<<(M_TOT*KK1 + 255)/256, 256>>>(xr, xi);
    pack_w1t<<<(NN1*KK1 + 255)/256, 256>>>(wq_r, wq_i, wkv_r, wkv_i);
    pack_w2t<<<(NN2*KK1 + 255)/256, 256>>>(wo_r, wo_i);
    gemm1_mma<<<dim3(NN1/64, M_TOT/64), 256>>>();
    attn_mma<<<dim3(16, 64), 128, SM_TOTAL>>>();
    gemm2_mma<<<dim3(NN2/64, M_TOT/64), 256>>>(out);
}

// round 14
// speedup vs baseline: 1.0661x; 1.0114x over previous
#include <cuda_runtime.h>
#include <cuda_fp16.h>
#include <cstdint>

#define BSZ 2
#define NSEQ 2048
#define DIMM 256
#define HH 8
#define DHD 32
#define M_TOT (BSZ*NSEQ)
#define KK1 512
#define NN1 1536
#define NN2 512

// ---------------- scratch ------------------------------------------------------
__device__ __align__(16) __half g_Xh[M_TOT*KK1];
__device__ __align__(16) __half g_W1th[NN1*KK1];
__device__ __align__(16) __half g_W1tl[NN1*KK1];
__device__ __align__(16) __half g_W2th[NN2*KK1];
__device__ __align__(16) __half g_W2tl[NN2*KK1];
__device__ __align__(16) __half g_Qrh[16*2048*32];
__device__ __align__(16) __half g_Qih[16*2048*32];
__device__ __align__(16) __half g_Krh[16*2048*32], g_Krl[16*2048*32];
__device__ __align__(16) __half g_Kih[16*2048*32], g_Kil[16*2048*32];
__device__ __align__(16) __half g_VTh[16*64*2048];          // [bh][d(vr|vi)][n]
__device__ __align__(16) __half g_Mh[M_TOT*KK1];            // [4096][512] (Mr|Mi) hi
__device__ __align__(16) __half g_Ml[M_TOT*KK1];            // lo

// ---------------- PTX helpers --------------------------------------------------
__device__ __forceinline__ uint32_t smem_u32(const void* p) {
    uint32_t a;
    asm("{ .reg .u64 t; cvta.to.shared.u64 t, %1; cvt.u32.u64 %0, t; }" : "=r"(a) : "l"(p));
    return a;
}
__device__ __forceinline__ void cp16(uint32_t dst, const void* src) {
    asm volatile("cp.async.cg.shared.global [%0], [%1], 16;" :: "r"(dst), "l"(src));
}
#define CP_COMMIT() asm volatile("cp.async.commit_group;" ::: "memory")
#define CP_WAIT0()  asm volatile("cp.async.wait_group 0;" ::: "memory")

__device__ __forceinline__ void ldm4(uint32_t* r, uint32_t addr) {
    asm volatile("ldmatrix.sync.aligned.m8n8.x4.shared.b16 {%0,%1,%2,%3}, [%4];"
        : "=r"(r[0]), "=r"(r[1]), "=r"(r[2]), "=r"(r[3]) : "r"(addr));
}
__device__ __forceinline__ void mma16816(float* d, const uint32_t* a, const uint32_t* b) {
    asm volatile("mma.sync.aligned.m16n8k16.row.col.f32.f16.f16.f32 "
        "{%0,%1,%2,%3}, {%4,%5,%6,%7}, {%8,%9}, {%0,%1,%2,%3};"
        : "+f"(d[0]), "+f"(d[1]), "+f"(d[2]), "+f"(d[3])
        : "r"(a[0]), "r"(a[1]), "r"(a[2]), "r"(a[3]), "r"(b[0]), "r"(b[1]));
}
__device__ __forceinline__ float ex2(float x) {
    float r; asm("ex2.approx.f32 %0, %1;" : "=f"(r) : "f"(x)); return r;
}
__device__ __forceinline__ uint32_t pk(float a, float b) {
    __half2 h = __floats2half2_rn(a, b);
    return *reinterpret_cast<uint32_t*>(&h);
}

// ---------------- fused input/weight packing -------------------------------------
// region 0: X split (2,097,152 elems) ; region 1: W1t (786,432) ; region 2: W2t (262,144)
#define PK_X  (M_TOT*KK1)
#define PK_W1 (NN1*KK1)
#define PK_W2 (NN2*KK1)
#define PK_TOT (PK_X + PK_W1 + PK_W2)

__global__ void pack_all(const float* __restrict__ xr, const float* __restrict__ xi,
                         const float* __restrict__ wq_r, const float* __restrict__ wq_i,
                         const float* __restrict__ wkv_r, const float* __restrict__ wkv_i,
                         const float* __restrict__ wo_r, const float* __restrict__ wo_i) {
    int idx = blockIdx.x*blockDim.x + threadIdx.x;
    if (idx < PK_X) {
        int m = idx >> 9, k = idx & 511;
        float v = (k < 256) ? xr[m*256 + k] : xi[m*256 + k - 256];
        g_Xh[idx] = __float2half_rn(v);
        return;
    }
    idx -= PK_X;
    if (idx < PK_W1) {
        int c = idx >> 9, k = idx & 511;
        int reg = c >> 8, cc = c & 255;
        bool top = (k < 256);
        int kr = k & 255;
        float v;
        switch (reg) {
            case 0: v = top ? wq_r[kr*256+cc]      : -wq_i[kr*256+cc];      break;
            case 1: v = top ? wq_i[kr*256+cc]      :  wq_r[kr*256+cc];      break;
            case 2: v = top ? wkv_r[kr*512+cc]     : -wkv_i[kr*512+cc];     break;
            case 3: v = top ? wkv_i[kr*512+cc]     :  wkv_r[kr*512+cc];     break;
            case 4: v = top ? wkv_r[kr*512+256+cc] : -wkv_i[kr*512+256+cc]; break;
            default:v = top ? wkv_i[kr*512+256+cc] :  wkv_r[kr*512+256+cc]; break;
        }
        __half hi = __float2half_rn(v);
        g_W1th[idx] = hi;
        g_W1tl[idx] = __float2half_rn(v - __half2float(hi));
        return;
    }
    idx -= PK_W1;
    if (idx < PK_W2) {
        int c = idx >> 9, k = idx & 511;
        bool top = (k < 256);
        int kr = k & 255, co = c & 255;
        float v;
        if (c < 256) v = top ? wo_r[kr*256+co] : -wo_i[kr*256+co];
        else         v = top ? wo_i[kr*256+co] :  wo_r[kr*256+co];
        __half hi = __float2half_rn(v);
        g_W2th[idx] = hi;
        g_W2tl[idx] = __float2half_rn(v - __half2float(hi));
    }
}

// ---------------- GEMM1: 2-pass  Xh @ (W1h + W1l), tile 64x64 -------------------
#define G1STG 15360

__global__ void __launch_bounds__(256, 3) gemm1_mma() {
    __shared__ __align__(16) unsigned char sm[2*G1STG];
    const int tid = threadIdx.x, w = tid >> 5, lane = tid & 31;
    const int wm = w & 3, wn = w >> 2;
    const int mBase = blockIdx.y * 64, nBase = blockIdx.x * 64;
    const uint32_t smb = smem_u32(sm);
    const int r8 = lane & 7, q = lane >> 3;

    auto prefetch = [&](int t) {
        int k0 = t * 32;
        uint32_t so = smb + (uint32_t)(t & 1) * G1STG;
        int row = tid >> 2, seg = tid & 3;
        size_t ga = (size_t)(mBase + row)*512 + k0 + seg*8;
        cp16(so + row*80 + seg*16, g_Xh + ga);
        size_t gb = (size_t)(nBase + row)*512 + k0 + seg*8;
        cp16(so + 5120 + row*80 + seg*16, g_W1th + gb);
        cp16(so + 10240 + row*80 + seg*16, g_W1tl + gb);
    };

    prefetch(0); CP_COMMIT();
    CP_WAIT0();
    __syncthreads();

    float Xc[4][4] = {};

    for (int t = 0; t < 16; t++) {
        uint32_t so = smb + (uint32_t)(t & 1) * G1STG;
        if (t < 15) { prefetch(t + 1); CP_COMMIT(); }

        uint32_t ah[2][4];
        #pragma unroll
        for (int ks = 0; ks < 2; ks++) {
            uint32_t ad = so + (uint32_t)(16*wm + r8 + (q & 1)*8)*80 + ks*32 + (q >> 1)*16;
            ldm4(ah[ks], ad);
        }
        #pragma unroll
        for (int nbp = 0; nbp < 2; nbp++) {
            #pragma unroll
            for (int ks = 0; ks < 2; ks++) {
                uint32_t ad = so + 5120
                            + (uint32_t)(wn*32 + nbp*16 + r8 + (q >> 1)*8)*80 + ks*32 + (q & 1)*16;
                uint32_t bh4[4], bl4[4];
                ldm4(bh4, ad);
                ldm4(bl4, ad + 5120);
                mma16816(Xc[2*nbp],   ah[ks], bh4);
                mma16816(Xc[2*nbp+1], ah[ks], bh4+2);
                mma16816(Xc[2*nbp],   ah[ks], bl4);
                mma16816(Xc[2*nbp+1], ah[ks], bl4+2);
            }
        }
        if (t < 15) { CP_WAIT0(); __syncthreads(); }
    }

    // ---- epilogue: Q hi only; K hi+lo; V transposed hi ----
    #pragma unroll
    for (int nf = 0; nf < 4; nf++) {
        #pragma unroll
        for (int e = 0; e < 4; e++) {
            int m = mBase + 16*wm + (e >> 1)*8 + (lane >> 2);
            int c = nBase + wn*32 + nf*8 + (lane & 3)*2 + (e & 1);
            float v = Xc[nf][e];
            int reg = c >> 8, rem = c & 255;
            int hd = rem >> 5, d = rem & 31;
            int b = m >> 11, n = m & 2047;
            int bhq = b*HH + hd;
            __half hi = __float2half_rn(v);
            size_t off = ((size_t)bhq*2048 + n)*32 + d;
            switch (reg) {
                case 0: g_Qrh[off] = hi; break;
                case 1: g_Qih[off] = hi; break;
                case 2: g_Krh[off] = hi; g_Krl[off] = __float2half_rn(v - __half2float(hi)); break;
                case 3: g_Kih[off] = hi; g_Kil[off] = __float2half_rn(v - __half2float(hi)); break;
                default:
                    g_VTh[((size_t)bhq*64 + (reg-4)*32 + d)*2048 + n] = hi;
            }
        }
    }
}

// ---------------- GEMM2: 3-pass (Mh/Ml) @ (W2h/W2l), tile 64x64 ------------------
#define G2STG 20480

__global__ void __launch_bounds__(256, 3) gemm2_mma(float* __restrict__ outp) {
    __shared__ __align__(16) unsigned char sm[2*G2STG];
    const int tid = threadIdx.x, w = tid >> 5, lane = tid & 31;
    const int wm = w & 3, wn = w >> 2;
    const int mBase = blockIdx.y * 64, nBase = blockIdx.x * 64;
    const uint32_t smb = smem_u32(sm);
    const int r8 = lane & 7, q = lane >> 3;

    auto prefetch = [&](int t) {
        int k0 = t * 32;
        uint32_t so = smb + (uint32_t)(t & 1) * G2STG;
        int row = tid >> 2, seg = tid & 3;
        size_t ga = (size_t)(mBase + row)*512 + k0 + seg*8;
        cp16(so + row*80 + seg*16, g_Mh + ga);
        cp16(so + 5120 + row*80 + seg*16, g_Ml + ga);
        size_t gb = (size_t)(nBase + row)*512 + k0 + seg*8;
        cp16(so + 10240 + row*80 + seg*16, g_W2th + gb);
        cp16(so + 15360 + row*80 + seg*16, g_W2tl + gb);
    };

    prefetch(0); CP_COMMIT();
    CP_WAIT0();
    __syncthreads();

    float Xc[4][4] = {};

    for (int t = 0; t < 16; t++) {
        uint32_t so = smb + (uint32_t)(t & 1) * G2STG;
        if (t < 15) { prefetch(t + 1); CP_COMMIT(); }

        uint32_t ah[2][4], al[2][4];
        #pragma unroll
        for (int ks = 0; ks < 2; ks++) {
            uint32_t ad = so + (uint32_t)(16*wm + r8 + (q & 1)*8)*80 + ks*32 + (q >> 1)*16;
            ldm4(ah[ks], ad);
            ldm4(al[ks], ad + 5120);
        }
        #pragma unroll
        for (int nbp = 0; nbp < 2; nbp++) {
            #pragma unroll
            for (int ks = 0; ks < 2; ks++) {
                uint32_t ad = so + 10240
                            + (uint32_t)(wn*32 + nbp*16 + r8 + (q >> 1)*8)*80 + ks*32 + (q & 1)*16;
                uint32_t bh4[4], bl4[4];
                ldm4(bh4, ad);
                ldm4(bl4, ad + 5120);
                mma16816(Xc[2*nbp],   ah[ks], bh4);
                mma16816(Xc[2*nbp+1], ah[ks], bh4+2);
                mma16816(Xc[2*nbp],   ah[ks], bl4);
                mma16816(Xc[2*nbp+1], ah[ks], bl4+2);
                mma16816(Xc[2*nbp],   al[ks], bh4);
                mma16816(Xc[2*nbp+1], al[ks], bh4+2);
            }
        }
        if (t < 15) { CP_WAIT0(); __syncthreads(); }
    }

    #pragma unroll
    for (int nf = 0; nf < 4; nf++) {
        #pragma unroll
        for (int e = 0; e < 4; e++) {
            int m = mBase + 16*wm + (e >> 1)*8 + (lane >> 2);
            int c = nBase + wn*32 + nf*8 + (lane & 3)*2 + (e & 1);
            outp[((size_t)m*DIMM + (c & 255))*2 + (c >> 8)] = Xc[nf][e];
        }
    }
}

// ---------------- HMMA attention (QK 2-pass, fp32 exp, interleaved PV) ----------
#define SLOT 29696
#define SM_TOTAL (2*SLOT)

__global__ void __launch_bounds__(128, 2) attn_mma() {
    extern __shared__ __align__(16) unsigned char sm[];
    const int tid = threadIdx.x, w = tid >> 5, lane = tid & 31;
    const int bh = blockIdx.x;
    const int row0 = blockIdx.y * 32;
    const uint32_t smb = smem_u32(sm);
    const int r8 = lane & 7, q = lane >> 3;

    auto prefetch = [&](int t) {
        int ct = t * 64;
        uint32_t so = smb + (uint32_t)(t & 1) * SLOT;
        #pragma unroll
        for (int i = 0; i < 4; i++) {
            int c = tid + (i << 7);
            int row = c >> 2, pc = c & 3;
            size_t soff = ((size_t)bh*2048 + ct + (row & 63))*32 + pc*8;
            const __half* sh = (row < 64) ? g_Krh : g_Kih;
            const __half* sl = (row < 64) ? g_Krl : g_Kil;
            cp16(so + row*80 + pc*16, sh + soff);
            cp16(so + 10240 + row*80 + pc*16, sl + soff);
        }
        #pragma unroll
        for (int i = 0; i < 4; i++) {
            int c = tid + (i << 7);
            int dd = c >> 3, pc = c & 7;
            cp16(so + 20480 + dd*144 + pc*16,
                 g_VTh + ((size_t)bh*64 + dd)*2048 + ct + pc*8);
        }
    };

    prefetch(0); CP_COMMIT();

    const __half* Qh = (w < 2) ? g_Qrh : g_Qih;
    size_t qoff = ((size_t)bh*2048 + row0 + (w & 1)*16 + (lane >> 2))*32 + (lane & 3)*2;
    uint32_t aqh[2][4];
    #pragma unroll
    for (int ks = 0; ks < 2; ks++) {
        aqh[ks][0] = *(const uint32_t*)(Qh + qoff + ks*16);
        aqh[ks][1] = *(const uint32_t*)(Qh + qoff + 256 + ks*16);
        aqh[ks][2] = *(const uint32_t*)(Qh + qoff + ks*16 + 8);
        aqh[ks][3] = *(const uint32_t*)(Qh + qoff + 256 + ks*16 + 8);
    }
    CP_WAIT0();
    __syncthreads();

    float X[8][4] = {};
    float Y[8][4] = {};
    float l00 = 0.f, l01 = 0.f, l10 = 0.f, l11 = 0.f;
    const float C = (float)(1.4426950408889634 / 5.656854249492380);
    const float SHIFT = 10.0f;

    for (int t = 0; t < 32; t++) {
        uint32_t so = smb + (uint32_t)(t & 1) * SLOT;
        if (t < 31) { prefetch(t + 1); CP_COMMIT(); }

        float S[16][4];
        #pragma unroll
        for (int nb = 0; nb < 16; nb++)
            #pragma unroll
            for (int e = 0; e < 4; e++) S[nb][e] = 0.f;

        #pragma unroll
        for (int nbp = 0; nbp < 8; nbp++) {
            #pragma unroll
            for (int ks = 0; ks < 2; ks++) {
                uint32_t ad = so + (uint32_t)(nbp*16 + r8 + (q >> 1)*8)*80 + ks*32 + (q & 1)*16;
                uint32_t bh4[4], bl4[4];
                ldm4(bh4, ad);
                ldm4(bl4, ad + 10240);
                mma16816(S[2*nbp],   aqh[ks], bh4);
                mma16816(S[2*nbp+1], aqh[ks], bh4+2);
                mma16816(S[2*nbp],   aqh[ks], bl4);
                mma16816(S[2*nbp+1], aqh[ks], bl4+2);
            }
        }

        uint32_t vt = so + 20480;
        #pragma unroll
        for (int h2 = 0; h2 < 2; h2++) {
            uint32_t Pf[4][4];
            float ls0 = 0.f, ls1 = 0.f;
            #pragma unroll
            for (int ks = 0; ks < 4; ks++) {
                int nb = 8*h2 + 2*ks;
                float p00 = ex2(fmaf(S[nb][0],   C, -SHIFT));
                float p01 = ex2(fmaf(S[nb][1],   C, -SHIFT));
                float p02 = ex2(fmaf(S[nb][2],   C, -SHIFT));
                float p03 = ex2(fmaf(S[nb][3],   C, -SHIFT));
                float p10 = ex2(fmaf(S[nb+1][0], C, -SHIFT));
                float p11 = ex2(fmaf(S[nb+1][1], C, -SHIFT));
                float p12 = ex2(fmaf(S[nb+1][2], C, -SHIFT));
                float p13 = ex2(fmaf(S[nb+1][3], C, -SHIFT));
                ls0 += p00 + p01 + p10 + p11;
                ls1 += p02 + p03 + p12 + p13;
                Pf[ks][0] = pk(p00, p01);
                Pf[ks][1] = pk(p02, p03);
                Pf[ks][2] = pk(p10, p11);
                Pf[ks][3] = pk(p12, p13);
            }
            if (h2 == 0) { l00 += ls0; l10 += ls1; }
            else         { l01 += ls0; l11 += ls1; }

            float (*Z)[4] = h2 ? Y : X;
            #pragma unroll
            for (int dbp = 0; dbp < 4; dbp++) {
                #pragma unroll
                for (int ks = 0; ks < 4; ks++) {
                    uint32_t ad = vt + (uint32_t)(dbp*16 + r8 + (q >> 1)*8)*144 + ks*32 + (q & 1)*16;
                    uint32_t bv[4];
                    ldm4(bv, ad);
                    mma16816(Z[2*dbp],   Pf[ks], bv);
                    mma16816(Z[2*dbp+1], Pf[ks], bv+2);
                }
            }
        }

        if (t < 31) { CP_WAIT0(); __syncthreads(); }
    }
    __syncthreads();

    l00 += __shfl_xor_sync(~0u, l00, 1); l00 += __shfl_xor_sync(~0u, l00, 2);
    l01 += __shfl_xor_sync(~0u, l01, 1); l01 += __shfl_xor_sync(~0u, l01, 2);
    l10 += __shfl_xor_sync(~0u, l10, 1); l10 += __shfl_xor_sync(~0u, l10, 2);
    l11 += __shfl_xor_sync(~0u, l11, 1); l11 += __shfl_xor_sync(~0u, l11, 2);
    float rl[2][2] = {{1.f/l00, 1.f/l01}, {1.f/l10, 1.f/l11}};

    float* orS = (float*)sm;             // [2][32][32]
    float* oiS = (float*)(sm + 8192);
    int grp = w >> 1;
    int mb = 16*(w & 1) + (lane >> 2);
    int dq = 2*(lane & 3);
    #pragma unroll
    for (int db = 0; db < 4; db++) {
        #pragma unroll
        for (int rr = 0; rr < 2; rr++) {
            #pragma unroll
            for (int dd = 0; dd < 2; dd++) {
                float x  = X[db][2*rr+dd]   * rl[rr][0];
                float x2 = X[db+4][2*rr+dd] * rl[rr][0];
                float y  = Y[db][2*rr+dd]   * rl[rr][1];
                float y2 = Y[db+4][2*rr+dd] * rl[rr][1];
                float orv = grp ? (-x2 - y) : (x - y2);
                float oiv = grp ? (x - y2)  : (x2 + y);
                int m = mb + rr*8, dcol = 8*db + dq + dd;
                orS[grp*1024 + m*32 + dcol] = orv;
                oiS[grp*1024 + m*32 + dcol] = oiv;
            }
        }
    }
    __syncthreads();
    {
        int b = bh >> 3, hh = bh & 7;
        for (int e = tid; e < 1024; e += 128) {
            int m = e >> 5, dcol = e & 31;
            float r  = orS[m*32 + dcol] + orS[1024 + m*32 + dcol];
            float im = oiS[m*32 + dcol] + oiS[1024 + m*32 + dcol];
            size_t o = ((size_t)(b*2048 + row0 + m))*512 + hh*32 + dcol;
            __half rh = __float2half_rn(r);
            __half ih = __float2half_rn(im);
            g_Mh[o]       = rh;
            g_Ml[o]       = __float2half_rn(r - __half2float(rh));
            g_Mh[o + 256] = ih;
            g_Ml[o + 256] = __float2half_rn(im - __half2float(ih));
        }
    }
}

// ---------------- launch -------------------------------------------------------------
extern "C" void kernel_launch(void* const* d_in, const int* in_sizes, int n_in,
                              void* d_out, int out_size) {
    const float* xr    = (const float*)d_in[0];
    const float* xi    = (const float*)d_in[1];
    const float* wq_r  = (const float*)d_in[2];
    const float* wq_i  = (const float*)d_in[3];
    const float* wkv_r = (const float*)d_in[4];
    const float* wkv_i = (const float*)d_in[5];
    const float* wo_r  = (const float*)d_in[6];
    const float* wo_i  = (const float*)d_in[7];
    float* out = (float*)d_out;

    cudaFuncSetAttribute(attn_mma, cudaFuncAttributeMaxDynamicSharedMemorySize, SM_TOTAL);

    pack_all<<<(PK_TOT + 255)/256, 256>>>(xr, xi, wq_r, wq_i, wkv_r, wkv_i, wo_r, wo_i);
    gemm1_mma<<<dim3(NN1/64, M_TOT/64), 256>>>();
    attn_mma<<<dim3(16, 64), 128, SM_TOTAL>>>();
    gemm2_mma<<<dim3(NN2/64, M_TOT/64), 256>>>(out);
}

// round 15
// speedup vs baseline: 1.1395x; 1.0688x over previous
#include <cuda_runtime.h>
#include <cuda_fp16.h>
#include <cstdint>

#define BSZ 2
#define NSEQ 2048
#define DIMM 256
#define HH 8
#define DHD 32
#define M_TOT (BSZ*NSEQ)
#define KK1 512
#define NN1 1536
#define NN2 512

// ---------------- scratch ------------------------------------------------------
__device__ __align__(16) __half g_Xh[M_TOT*KK1];
__device__ __align__(16) __half g_W1th[NN1*KK1];
__device__ __align__(16) __half g_W1tl[NN1*KK1];
__device__ __align__(16) __half g_W2th[NN2*KK1];
__device__ __align__(16) __half g_W2tl[NN2*KK1];
__device__ __align__(16) __half g_Qrh[16*2048*32];
__device__ __align__(16) __half g_Qih[16*2048*32];
__device__ __align__(16) __half g_Krh[16*2048*32], g_Krl[16*2048*32];
__device__ __align__(16) __half g_Kih[16*2048*32], g_Kil[16*2048*32];
__device__ __align__(16) __half g_VTh[16*64*2048];          // [bh][d(vr|vi)][n]
__device__ __align__(16) __half g_Mh[M_TOT*KK1];            // [4096][512] (Mr|Mi) hi
__device__ __align__(16) __half g_Ml[M_TOT*KK1];            // lo

// ---------------- PTX helpers --------------------------------------------------
__device__ __forceinline__ uint32_t smem_u32(const void* p) {
    uint32_t a;
    asm("{ .reg .u64 t; cvta.to.shared.u64 t, %1; cvt.u32.u64 %0, t; }" : "=r"(a) : "l"(p));
    return a;
}
__device__ __forceinline__ void cp16(uint32_t dst, const void* src) {
    asm volatile("cp.async.cg.shared.global [%0], [%1], 16;" :: "r"(dst), "l"(src));
}
#define CP_COMMIT() asm volatile("cp.async.commit_group;" ::: "memory")
#define CP_WAIT0()  asm volatile("cp.async.wait_group 0;" ::: "memory")
#define CP_WAIT1()  asm volatile("cp.async.wait_group 1;" ::: "memory")

__device__ __forceinline__ void ldm4(uint32_t* r, uint32_t addr) {
    asm volatile("ldmatrix.sync.aligned.m8n8.x4.shared.b16 {%0,%1,%2,%3}, [%4];"
        : "=r"(r[0]), "=r"(r[1]), "=r"(r[2]), "=r"(r[3]) : "r"(addr));
}
__device__ __forceinline__ void mma16816(float* d, const uint32_t* a, const uint32_t* b) {
    asm volatile("mma.sync.aligned.m16n8k16.row.col.f32.f16.f16.f32 "
        "{%0,%1,%2,%3}, {%4,%5,%6,%7}, {%8,%9}, {%0,%1,%2,%3};"
        : "+f"(d[0]), "+f"(d[1]), "+f"(d[2]), "+f"(d[3])
        : "r"(a[0]), "r"(a[1]), "r"(a[2]), "r"(a[3]), "r"(b[0]), "r"(b[1]));
}
__device__ __forceinline__ float ex2(float x) {
    float r; asm("ex2.approx.f32 %0, %1;" : "=f"(r) : "f"(x)); return r;
}
__device__ __forceinline__ uint32_t pk(float a, float b) {
    __half2 h = __floats2half2_rn(a, b);
    return *reinterpret_cast<uint32_t*>(&h);
}

// ---------------- fused input/weight packing -------------------------------------
#define PK_X  (M_TOT*KK1)
#define PK_W1 (NN1*KK1)
#define PK_W2 (NN2*KK1)
#define PK_TOT (PK_X + PK_W1 + PK_W2)

__global__ void pack_all(const float* __restrict__ xr, const float* __restrict__ xi,
                         const float* __restrict__ wq_r, const float* __restrict__ wq_i,
                         const float* __restrict__ wkv_r, const float* __restrict__ wkv_i,
                         const float* __restrict__ wo_r, const float* __restrict__ wo_i) {
    int idx = blockIdx.x*blockDim.x + threadIdx.x;
    if (idx < PK_X) {
        int m = idx >> 9, k = idx & 511;
        float v = (k < 256) ? xr[m*256 + k] : xi[m*256 + k - 256];
        g_Xh[idx] = __float2half_rn(v);
        return;
    }
    idx -= PK_X;
    if (idx < PK_W1) {
        int c = idx >> 9, k = idx & 511;
        int reg = c >> 8, cc = c & 255;
        bool top = (k < 256);
        int kr = k & 255;
        float v;
        switch (reg) {
            case 0: v = top ? wq_r[kr*256+cc]      : -wq_i[kr*256+cc];      break;
            case 1: v = top ? wq_i[kr*256+cc]      :  wq_r[kr*256+cc];      break;
            case 2: v = top ? wkv_r[kr*512+cc]     : -wkv_i[kr*512+cc];     break;
            case 3: v = top ? wkv_i[kr*512+cc]     :  wkv_r[kr*512+cc];     break;
            case 4: v = top ? wkv_r[kr*512+256+cc] : -wkv_i[kr*512+256+cc]; break;
            default:v = top ? wkv_i[kr*512+256+cc] :  wkv_r[kr*512+256+cc]; break;
        }
        __half hi = __float2half_rn(v);
        g_W1th[idx] = hi;
        g_W1tl[idx] = __float2half_rn(v - __half2float(hi));
        return;
    }
    idx -= PK_W1;
    if (idx < PK_W2) {
        int c = idx >> 9, k = idx & 511;
        bool top = (k < 256);
        int kr = k & 255, co = c & 255;
        float v;
        if (c < 256) v = top ? wo_r[kr*256+co] : -wo_i[kr*256+co];
        else         v = top ? wo_i[kr*256+co] :  wo_r[kr*256+co];
        __half hi = __float2half_rn(v);
        g_W2th[idx] = hi;
        g_W2tl[idx] = __float2half_rn(v - __half2float(hi));
    }
}

// ---------------- GEMM1: 2-pass  Xh @ (W1h + W1l), tile 64x64, 3-stage -----------
#define G1STG 15360

__global__ void __launch_bounds__(256, 3) gemm1_mma() {
    __shared__ __align__(16) unsigned char sm[3*G1STG];
    const int tid = threadIdx.x, w = tid >> 5, lane = tid & 31;
    const int wm = w & 3, wn = w >> 2;
    const int mBase = blockIdx.y * 64, nBase = blockIdx.x * 64;
    const uint32_t smb = smem_u32(sm);
    const int r8 = lane & 7, q = lane >> 3;

    auto prefetch = [&](int t) {
        int k0 = t * 32;
        uint32_t so = smb + (uint32_t)(t % 3) * G1STG;
        int row = tid >> 2, seg = tid & 3;
        size_t ga = (size_t)(mBase + row)*512 + k0 + seg*8;
        cp16(so + row*80 + seg*16, g_Xh + ga);
        size_t gb = (size_t)(nBase + row)*512 + k0 + seg*8;
        cp16(so + 5120 + row*80 + seg*16, g_W1th + gb);
        cp16(so + 10240 + row*80 + seg*16, g_W1tl + gb);
    };

    prefetch(0); CP_COMMIT();
    prefetch(1); CP_COMMIT();

    float Xc[4][4] = {};

    for (int t = 0; t < 16; t++) {
        if (t < 15) CP_WAIT1(); else CP_WAIT0();
        __syncthreads();
        if (t + 2 < 16) { prefetch(t + 2); CP_COMMIT(); }
        uint32_t so = smb + (uint32_t)(t % 3) * G1STG;

        uint32_t ah[2][4];
        #pragma unroll
        for (int ks = 0; ks < 2; ks++) {
            uint32_t ad = so + (uint32_t)(16*wm + r8 + (q & 1)*8)*80 + ks*32 + (q >> 1)*16;
            ldm4(ah[ks], ad);
        }
        #pragma unroll
        for (int nbp = 0; nbp < 2; nbp++) {
            #pragma unroll
            for (int ks = 0; ks < 2; ks++) {
                uint32_t ad = so + 5120
                            + (uint32_t)(wn*32 + nbp*16 + r8 + (q >> 1)*8)*80 + ks*32 + (q & 1)*16;
                uint32_t bh4[4], bl4[4];
                ldm4(bh4, ad);
                ldm4(bl4, ad + 5120);
                mma16816(Xc[2*nbp],   ah[ks], bh4);
                mma16816(Xc[2*nbp+1], ah[ks], bh4+2);
                mma16816(Xc[2*nbp],   ah[ks], bl4);
                mma16816(Xc[2*nbp+1], ah[ks], bl4+2);
            }
        }
    }

    // ---- epilogue: Q hi only; K hi+lo; V transposed hi ----
    #pragma unroll
    for (int nf = 0; nf < 4; nf++) {
        #pragma unroll
        for (int e = 0; e < 4; e++) {
            int m = mBase + 16*wm + (e >> 1)*8 + (lane >> 2);
            int c = nBase + wn*32 + nf*8 + (lane & 3)*2 + (e & 1);
            float v = Xc[nf][e];
            int reg = c >> 8, rem = c & 255;
            int hd = rem >> 5, d = rem & 31;
            int b = m >> 11, n = m & 2047;
            int bhq = b*HH + hd;
            __half hi = __float2half_rn(v);
            size_t off = ((size_t)bhq*2048 + n)*32 + d;
            switch (reg) {
                case 0: g_Qrh[off] = hi; break;
                case 1: g_Qih[off] = hi; break;
                case 2: g_Krh[off] = hi; g_Krl[off] = __float2half_rn(v - __half2float(hi)); break;
                case 3: g_Kih[off] = hi; g_Kil[off] = __float2half_rn(v - __half2float(hi)); break;
                default:
                    g_VTh[((size_t)bhq*64 + (reg-4)*32 + d)*2048 + n] = hi;
            }
        }
    }
}

// ---------------- GEMM2: 3-pass (Mh/Ml) @ (W2h/W2l), tile 64x64, 3-stage ---------
#define G2STG 20480
#define G2SM (3*G2STG)

__global__ void __launch_bounds__(256, 3) gemm2_mma(float* __restrict__ outp) {
    extern __shared__ __align__(16) unsigned char smd[];
    const int tid = threadIdx.x, w = tid >> 5, lane = tid & 31;
    const int wm = w & 3, wn = w >> 2;
    const int mBase = blockIdx.y * 64, nBase = blockIdx.x * 64;
    const uint32_t smb = smem_u32(smd);
    const int r8 = lane & 7, q = lane >> 3;

    auto prefetch = [&](int t) {
        int k0 = t * 32;
        uint32_t so = smb + (uint32_t)(t % 3) * G2STG;
        int row = tid >> 2, seg = tid & 3;
        size_t ga = (size_t)(mBase + row)*512 + k0 + seg*8;
        cp16(so + row*80 + seg*16, g_Mh + ga);
        cp16(so + 5120 + row*80 + seg*16, g_Ml + ga);
        size_t gb = (size_t)(nBase + row)*512 + k0 + seg*8;
        cp16(so + 10240 + row*80 + seg*16, g_W2th + gb);
        cp16(so + 15360 + row*80 + seg*16, g_W2tl + gb);
    };

    prefetch(0); CP_COMMIT();
    prefetch(1); CP_COMMIT();

    float Xc[4][4] = {};

    for (int t = 0; t < 16; t++) {
        if (t < 15) CP_WAIT1(); else CP_WAIT0();
        __syncthreads();
        if (t + 2 < 16) { prefetch(t + 2); CP_COMMIT(); }
        uint32_t so = smb + (uint32_t)(t % 3) * G2STG;

        uint32_t ah[2][4], al[2][4];
        #pragma unroll
        for (int ks = 0; ks < 2; ks++) {
            uint32_t ad = so + (uint32_t)(16*wm + r8 + (q & 1)*8)*80 + ks*32 + (q >> 1)*16;
            ldm4(ah[ks], ad);
            ldm4(al[ks], ad + 5120);
        }
        #pragma unroll
        for (int nbp = 0; nbp < 2; nbp++) {
            #pragma unroll
            for (int ks = 0; ks < 2; ks++) {
                uint32_t ad = so + 10240
                            + (uint32_t)(wn*32 + nbp*16 + r8 + (q >> 1)*8)*80 + ks*32 + (q & 1)*16;
                uint32_t bh4[4], bl4[4];
                ldm4(bh4, ad);
                ldm4(bl4, ad + 5120);
                mma16816(Xc[2*nbp],   ah[ks], bh4);
                mma16816(Xc[2*nbp+1], ah[ks], bh4+2);
                mma16816(Xc[2*nbp],   ah[ks], bl4);
                mma16816(Xc[2*nbp+1], ah[ks], bl4+2);
                mma16816(Xc[2*nbp],   al[ks], bh4);
                mma16816(Xc[2*nbp+1], al[ks], bh4+2);
            }
        }
    }

    #pragma unroll
    for (int nf = 0; nf < 4; nf++) {
        #pragma unroll
        for (int e = 0; e < 4; e++) {
            int m = mBase + 16*wm + (e >> 1)*8 + (lane >> 2);
            int c = nBase + wn*32 + nf*8 + (lane & 3)*2 + (e & 1);
            outp[((size_t)m*DIMM + (c & 255))*2 + (c >> 8)] = Xc[nf][e];
        }
    }
}

// ---------------- HMMA attention (QK 2-pass, 3-stage pipeline) -------------------
#define SLOT 29696
#define SM_TOTAL (3*SLOT)

__global__ void __launch_bounds__(128, 2) attn_mma() {
    extern __shared__ __align__(16) unsigned char sm[];
    const int tid = threadIdx.x, w = tid >> 5, lane = tid & 31;
    const int bh = blockIdx.x;
    const int row0 = blockIdx.y * 32;
    const uint32_t smb = smem_u32(sm);
    const int r8 = lane & 7, q = lane >> 3;

    auto prefetch = [&](int t) {
        int ct = t * 64;
        uint32_t so = smb + (uint32_t)(t % 3) * SLOT;
        #pragma unroll
        for (int i = 0; i < 4; i++) {
            int c = tid + (i << 7);
            int row = c >> 2, pc = c & 3;
            size_t soff = ((size_t)bh*2048 + ct + (row & 63))*32 + pc*8;
            const __half* sh = (row < 64) ? g_Krh : g_Kih;
            const __half* sl = (row < 64) ? g_Krl : g_Kil;
            cp16(so + row*80 + pc*16, sh + soff);
            cp16(so + 10240 + row*80 + pc*16, sl + soff);
        }
        #pragma unroll
        for (int i = 0; i < 4; i++) {
            int c = tid + (i << 7);
            int dd = c >> 3, pc = c & 7;
            cp16(so + 20480 + dd*144 + pc*16,
                 g_VTh + ((size_t)bh*64 + dd)*2048 + ct + pc*8);
        }
    };

    prefetch(0); CP_COMMIT();
    prefetch(1); CP_COMMIT();

    const __half* Qh = (w < 2) ? g_Qrh : g_Qih;
    size_t qoff = ((size_t)bh*2048 + row0 + (w & 1)*16 + (lane >> 2))*32 + (lane & 3)*2;
    uint32_t aqh[2][4];
    #pragma unroll
    for (int ks = 0; ks < 2; ks++) {
        aqh[ks][0] = *(const uint32_t*)(Qh + qoff + ks*16);
        aqh[ks][1] = *(const uint32_t*)(Qh + qoff + 256 + ks*16);
        aqh[ks][2] = *(const uint32_t*)(Qh + qoff + ks*16 + 8);
        aqh[ks][3] = *(const uint32_t*)(Qh + qoff + 256 + ks*16 + 8);
    }

    float X[8][4] = {};
    float Y[8][4] = {};
    float l00 = 0.f, l01 = 0.f, l10 = 0.f, l11 = 0.f;
    const float C = (float)(1.4426950408889634 / 5.656854249492380);
    const float SHIFT = 10.0f;

    for (int t = 0; t < 32; t++) {
        if (t < 31) CP_WAIT1(); else CP_WAIT0();
        __syncthreads();
        if (t + 2 < 32) { prefetch(t + 2); CP_COMMIT(); }
        uint32_t so = smb + (uint32_t)(t % 3) * SLOT;

        float S[16][4];
        #pragma unroll
        for (int nb = 0; nb < 16; nb++)
            #pragma unroll
            for (int e = 0; e < 4; e++) S[nb][e] = 0.f;

        #pragma unroll
        for (int nbp = 0; nbp < 8; nbp++) {
            #pragma unroll
            for (int ks = 0; ks < 2; ks++) {
                uint32_t ad = so + (uint32_t)(nbp*16 + r8 + (q >> 1)*8)*80 + ks*32 + (q & 1)*16;
                uint32_t bh4[4], bl4[4];
                ldm4(bh4, ad);
                ldm4(bl4, ad + 10240);
                mma16816(S[2*nbp],   aqh[ks], bh4);
                mma16816(S[2*nbp+1], aqh[ks], bh4+2);
                mma16816(S[2*nbp],   aqh[ks], bl4);
                mma16816(S[2*nbp+1], aqh[ks], bl4+2);
            }
        }

        uint32_t vt = so + 20480;
        #pragma unroll
        for (int h2 = 0; h2 < 2; h2++) {
            uint32_t Pf[4][4];
            float ls0 = 0.f, ls1 = 0.f;
            #pragma unroll
            for (int ks = 0; ks < 4; ks++) {
                int nb = 8*h2 + 2*ks;
                float p00 = ex2(fmaf(S[nb][0],   C, -SHIFT));
                float p01 = ex2(fmaf(S[nb][1],   C, -SHIFT));
                float p02 = ex2(fmaf(S[nb][2],   C, -SHIFT));
                float p03 = ex2(fmaf(S[nb][3],   C, -SHIFT));
                float p10 = ex2(fmaf(S[nb+1][0], C, -SHIFT));
                float p11 = ex2(fmaf(S[nb+1][1], C, -SHIFT));
                float p12 = ex2(fmaf(S[nb+1][2], C, -SHIFT));
                float p13 = ex2(fmaf(S[nb+1][3], C, -SHIFT));
                ls0 += p00 + p01 + p10 + p11;
                ls1 += p02 + p03 + p12 + p13;
                Pf[ks][0] = pk(p00, p01);
                Pf[ks][1] = pk(p02, p03);
                Pf[ks][2] = pk(p10, p11);
                Pf[ks][3] = pk(p12, p13);
            }
            if (h2 == 0) { l00 += ls0; l10 += ls1; }
            else         { l01 += ls0; l11 += ls1; }

            float (*Z)[4] = h2 ? Y : X;
            #pragma unroll
            for (int dbp = 0; dbp < 4; dbp++) {
                #pragma unroll
                for (int ks = 0; ks < 4; ks++) {
                    uint32_t ad = vt + (uint32_t)(dbp*16 + r8 + (q >> 1)*8)*144 + ks*32 + (q & 1)*16;
                    uint32_t bv[4];
                    ldm4(bv, ad);
                    mma16816(Z[2*dbp],   Pf[ks], bv);
                    mma16816(Z[2*dbp+1], Pf[ks], bv+2);
                }
            }
        }
    }
    __syncthreads();

    l00 += __shfl_xor_sync(~0u, l00, 1); l00 += __shfl_xor_sync(~0u, l00, 2);
    l01 += __shfl_xor_sync(~0u, l01, 1); l01 += __shfl_xor_sync(~0u, l01, 2);
    l10 += __shfl_xor_sync(~0u, l10, 1); l10 += __shfl_xor_sync(~0u, l10, 2);
    l11 += __shfl_xor_sync(~0u, l11, 1); l11 += __shfl_xor_sync(~0u, l11, 2);
    float rl[2][2] = {{1.f/l00, 1.f/l01}, {1.f/l10, 1.f/l11}};

    float* orS = (float*)sm;             // [2][32][32]
    float* oiS = (float*)(sm + 8192);
    int grp = w >> 1;
    int mb = 16*(w & 1) + (lane >> 2);
    int dq = 2*(lane & 3);
    #pragma unroll
    for (int db = 0; db < 4; db++) {
        #pragma unroll
        for (int rr = 0; rr < 2; rr++) {
            #pragma unroll
            for (int dd = 0; dd < 2; dd++) {
                float x  = X[db][2*rr+dd]   * rl[rr][0];
                float x2 = X[db+4][2*rr+dd] * rl[rr][0];
                float y  = Y[db][2*rr+dd]   * rl[rr][1];
                float y2 = Y[db+4][2*rr+dd] * rl[rr][1];
                float orv = grp ? (-x2 - y) : (x - y2);
                float oiv = grp ? (x - y2)  : (x2 + y);
                int m = mb + rr*8, dcol = 8*db + dq + dd;
                orS[grp*1024 + m*32 + dcol] = orv;
                oiS[grp*1024 + m*32 + dcol] = oiv;
            }
        }
    }
    __syncthreads();
    {
        int b = bh >> 3, hh = bh & 7;
        for (int e = tid; e < 1024; e += 128) {
            int m = e >> 5, dcol = e & 31;
            float r  = orS[m*32 + dcol] + orS[1024 + m*32 + dcol];
            float im = oiS[m*32 + dcol] + oiS[1024 + m*32 + dcol];
            size_t o = ((size_t)(b*2048 + row0 + m))*512 + hh*32 + dcol;
            __half rh = __float2half_rn(r);
            __half ih = __float2half_rn(im);
            g_Mh[o]       = rh;
            g_Ml[o]       = __float2half_rn(r - __half2float(rh));
            g_Mh[o + 256] = ih;
            g_Ml[o + 256] = __float2half_rn(im - __half2float(ih));
        }
    }
}

// ---------------- launch -------------------------------------------------------------
extern "C" void kernel_launch(void* const* d_in, const int* in_sizes, int n_in,
                              void* d_out, int out_size) {
    const float* xr    = (const float*)d_in[0];
    const float* xi    = (const float*)d_in[1];
    const float* wq_r  = (const float*)d_in[2];
    const float* wq_i  = (const float*)d_in[3];
    const float* wkv_r = (const float*)d_in[4];
    const float* wkv_i = (const float*)d_in[5];
    const float* wo_r  = (const float*)d_in[6];
    const float* wo_i  = (const float*)d_in[7];
    float* out = (float*)d_out;

    cudaFuncSetAttribute(attn_mma, cudaFuncAttributeMaxDynamicSharedMemorySize, SM_TOTAL);
    cudaFuncSetAttribute(gemm2_mma, cudaFuncAttributeMaxDynamicSharedMemorySize, G2SM);

    pack_all<<<(PK_TOT + 255)/256, 256>>>(xr, xi, wq_r, wq_i, wkv_r, wkv_i, wo_r, wo_i);
    gemm1_mma<<<dim3(NN1/64, M_TOT/64), 256>>>();
    attn_mma<<<dim3(16, 64), 128, SM_TOTAL>>>();
    gemm2_mma<<<dim3(NN2/64, M_TOT/64), 256, G2SM>>>(out);
}

// round 16
// speedup vs baseline: 1.1498x; 1.0091x over previous
#include <cuda_runtime.h>
#include <cuda_fp16.h>
#include <cstdint>

#define BSZ 2
#define NSEQ 2048
#define DIMM 256
#define HH 8
#define DHD 32
#define M_TOT (BSZ*NSEQ)
#define KK1 512
#define NN1 1536
#define NN2 512

// ---------------- scratch ------------------------------------------------------
__device__ __align__(16) __half g_Xh[M_TOT*KK1];
__device__ __align__(16) __half g_W1th[NN1*KK1];
__device__ __align__(16) __half g_W1tl[NN1*KK1];
__device__ __align__(16) __half g_W2th[NN2*KK1];
__device__ __align__(16) __half g_W2tl[NN2*KK1];
__device__ __align__(16) __half g_Qrh[16*2048*32];
__device__ __align__(16) __half g_Qih[16*2048*32];
__device__ __align__(16) __half g_Krh[16*2048*32], g_Krl[16*2048*32];
__device__ __align__(16) __half g_Kih[16*2048*32], g_Kil[16*2048*32];
__device__ __align__(16) __half g_VTh[16*64*2048];          // [bh][d(vr|vi)][n]
__device__ __align__(16) __half g_Mh[M_TOT*KK1];            // [4096][512] (Mr|Mi) hi
__device__ __align__(16) __half g_Ml[M_TOT*KK1];            // lo

// ---------------- PTX helpers --------------------------------------------------
__device__ __forceinline__ uint32_t smem_u32(const void* p) {
    uint32_t a;
    asm("{ .reg .u64 t; cvta.to.shared.u64 t, %1; cvt.u32.u64 %0, t; }" : "=r"(a) : "l"(p));
    return a;
}
__device__ __forceinline__ void cp16(uint32_t dst, const void* src) {
    asm volatile("cp.async.cg.shared.global [%0], [%1], 16;" :: "r"(dst), "l"(src));
}
#define CP_COMMIT() asm volatile("cp.async.commit_group;" ::: "memory")
#define CP_WAIT0()  asm volatile("cp.async.wait_group 0;" ::: "memory")
#define CP_WAIT1()  asm volatile("cp.async.wait_group 1;" ::: "memory")

__device__ __forceinline__ void ldm4(uint32_t* r, uint32_t addr) {
    asm volatile("ldmatrix.sync.aligned.m8n8.x4.shared.b16 {%0,%1,%2,%3}, [%4];"
        : "=r"(r[0]), "=r"(r[1]), "=r"(r[2]), "=r"(r[3]) : "r"(addr));
}
__device__ __forceinline__ void mma16816(float* d, const uint32_t* a, const uint32_t* b) {
    asm volatile("mma.sync.aligned.m16n8k16.row.col.f32.f16.f16.f32 "
        "{%0,%1,%2,%3}, {%4,%5,%6,%7}, {%8,%9}, {%0,%1,%2,%3};"
        : "+f"(d[0]), "+f"(d[1]), "+f"(d[2]), "+f"(d[3])
        : "r"(a[0]), "r"(a[1]), "r"(a[2]), "r"(a[3]), "r"(b[0]), "r"(b[1]));
}
__device__ __forceinline__ float ex2(float x) {
    float r; asm("ex2.approx.f32 %0, %1;" : "=f"(r) : "f"(x)); return r;
}
__device__ __forceinline__ uint32_t pk(float a, float b) {
    __half2 h = __floats2half2_rn(a, b);
    return *reinterpret_cast<uint32_t*>(&h);
}

// ---------------- fused input/weight packing -------------------------------------
#define PK_X  (M_TOT*KK1)
#define PK_W1 (NN1*KK1)
#define PK_W2 (NN2*KK1)
#define PK_TOT (PK_X + PK_W1 + PK_W2)

__global__ void pack_all(const float* __restrict__ xr, const float* __restrict__ xi,
                         const float* __restrict__ wq_r, const float* __restrict__ wq_i,
                         const float* __restrict__ wkv_r, const float* __restrict__ wkv_i,
                         const float* __restrict__ wo_r, const float* __restrict__ wo_i) {
    int idx = blockIdx.x*blockDim.x + threadIdx.x;
    if (idx < PK_X) {
        int m = idx >> 9, k = idx & 511;
        float v = (k < 256) ? xr[m*256 + k] : xi[m*256 + k - 256];
        g_Xh[idx] = __float2half_rn(v);
        return;
    }
    idx -= PK_X;
    if (idx < PK_W1) {
        int c = idx >> 9, k = idx & 511;
        int reg = c >> 8, cc = c & 255;
        bool top = (k < 256);
        int kr = k & 255;
        float v;
        switch (reg) {
            case 0: v = top ? wq_r[kr*256+cc]      : -wq_i[kr*256+cc];      break;
            case 1: v = top ? wq_i[kr*256+cc]      :  wq_r[kr*256+cc];      break;
            case 2: v = top ? wkv_r[kr*512+cc]     : -wkv_i[kr*512+cc];     break;
            case 3: v = top ? wkv_i[kr*512+cc]     :  wkv_r[kr*512+cc];     break;
            case 4: v = top ? wkv_r[kr*512+256+cc] : -wkv_i[kr*512+256+cc]; break;
            default:v = top ? wkv_i[kr*512+256+cc] :  wkv_r[kr*512+256+cc]; break;
        }
        __half hi = __float2half_rn(v);
        g_W1th[idx] = hi;
        g_W1tl[idx] = __float2half_rn(v - __half2float(hi));
        return;
    }
    idx -= PK_W1;
    if (idx < PK_W2) {
        int c = idx >> 9, k = idx & 511;
        bool top = (k < 256);
        int kr = k & 255, co = c & 255;
        float v;
        if (c < 256) v = top ? wo_r[kr*256+co] : -wo_i[kr*256+co];
        else         v = top ? wo_i[kr*256+co] :  wo_r[kr*256+co];
        __half hi = __float2half_rn(v);
        g_W2th[idx] = hi;
        g_W2tl[idx] = __float2half_rn(v - __half2float(hi));
    }
}

// ---------------- GEMM1: 2-pass  Xh @ (W1h + W1l), tile 64x64, k64 chunks --------
// stage (k=64): A[64][144B] @0 (9216) | Bh @9216 | Bl @18432 ; 27648/stage, 2 stages
#define G1STG 27648
#define G1SM (2*G1STG)

__global__ void __launch_bounds__(256, 3) gemm1_mma() {
    extern __shared__ __align__(16) unsigned char smd[];
    const int tid = threadIdx.x, w = tid >> 5, lane = tid & 31;
    const int wm = w & 3, wn = w >> 2;
    const int mBase = blockIdx.y * 64, nBase = blockIdx.x * 64;
    const uint32_t smb = smem_u32(smd);
    const int r8 = lane & 7, q = lane >> 3;

    auto prefetch = [&](int t) {
        int k0 = t * 64;
        uint32_t so = smb + (uint32_t)(t & 1) * G1STG;
        #pragma unroll
        for (int i = 0; i < 2; i++) {
            int idx = tid + (i << 8);
            int row = idx >> 3, seg = idx & 7;
            size_t ga = (size_t)(mBase + row)*512 + k0 + seg*8;
            cp16(so + row*144 + seg*16, g_Xh + ga);
            size_t gb = (size_t)(nBase + row)*512 + k0 + seg*8;
            cp16(so + 9216 + row*144 + seg*16, g_W1th + gb);
            cp16(so + 18432 + row*144 + seg*16, g_W1tl + gb);
        }
    };

    prefetch(0); CP_COMMIT();

    float Xc[4][4] = {};

    for (int t = 0; t < 8; t++) {
        CP_WAIT0();
        __syncthreads();
        if (t + 1 < 8) { prefetch(t + 1); CP_COMMIT(); }
        uint32_t so = smb + (uint32_t)(t & 1) * G1STG;

        uint32_t ah[4][4];
        #pragma unroll
        for (int ks = 0; ks < 4; ks++) {
            uint32_t ad = so + (uint32_t)(16*wm + r8 + (q & 1)*8)*144 + ks*32 + (q >> 1)*16;
            ldm4(ah[ks], ad);
        }
        #pragma unroll
        for (int nbp = 0; nbp < 2; nbp++) {
            #pragma unroll
            for (int ks = 0; ks < 4; ks++) {
                uint32_t ad = so + 9216
                            + (uint32_t)(wn*32 + nbp*16 + r8 + (q >> 1)*8)*144 + ks*32 + (q & 1)*16;
                uint32_t bh4[4], bl4[4];
                ldm4(bh4, ad);
                ldm4(bl4, ad + 9216);
                mma16816(Xc[2*nbp],   ah[ks], bh4);
                mma16816(Xc[2*nbp+1], ah[ks], bh4+2);
                mma16816(Xc[2*nbp],   ah[ks], bl4);
                mma16816(Xc[2*nbp+1], ah[ks], bl4+2);
            }
        }
    }

    // ---- epilogue: Q hi only; K hi+lo; V transposed hi ----
    #pragma unroll
    for (int nf = 0; nf < 4; nf++) {
        #pragma unroll
        for (int e = 0; e < 4; e++) {
            int m = mBase + 16*wm + (e >> 1)*8 + (lane >> 2);
            int c = nBase + wn*32 + nf*8 + (lane & 3)*2 + (e & 1);
            float v = Xc[nf][e];
            int reg = c >> 8, rem = c & 255;
            int hd = rem >> 5, d = rem & 31;
            int b = m >> 11, n = m & 2047;
            int bhq = b*HH + hd;
            __half hi = __float2half_rn(v);
            size_t off = ((size_t)bhq*2048 + n)*32 + d;
            switch (reg) {
                case 0: g_Qrh[off] = hi; break;
                case 1: g_Qih[off] = hi; break;
                case 2: g_Krh[off] = hi; g_Krl[off] = __float2half_rn(v - __half2float(hi)); break;
                case 3: g_Kih[off] = hi; g_Kil[off] = __float2half_rn(v - __half2float(hi)); break;
                default:
                    g_VTh[((size_t)bhq*64 + (reg-4)*32 + d)*2048 + n] = hi;
            }
        }
    }
}

// ---------------- GEMM2: 3-pass (Mh/Ml) @ (W2h/W2l), tile 64x64, k64 chunks ------
// stage: Mh @0 | Ml @9216 | W2h @18432 | W2l @27648 ; 36864/stage, 2 stages
#define G2STG 36864
#define G2SM (2*G2STG)

__global__ void __launch_bounds__(256, 3) gemm2_mma(float* __restrict__ outp) {
    extern __shared__ __align__(16) unsigned char smd[];
    const int tid = threadIdx.x, w = tid >> 5, lane = tid & 31;
    const int wm = w & 3, wn = w >> 2;
    const int mBase = blockIdx.y * 64, nBase = blockIdx.x * 64;
    const uint32_t smb = smem_u32(smd);
    const int r8 = lane & 7, q = lane >> 3;

    auto prefetch = [&](int t) {
        int k0 = t * 64;
        uint32_t so = smb + (uint32_t)(t & 1) * G2STG;
        #pragma unroll
        for (int i = 0; i < 2; i++) {
            int idx = tid + (i << 8);
            int row = idx >> 3, seg = idx & 7;
            size_t ga = (size_t)(mBase + row)*512 + k0 + seg*8;
            cp16(so + row*144 + seg*16, g_Mh + ga);
            cp16(so + 9216 + row*144 + seg*16, g_Ml + ga);
            size_t gb = (size_t)(nBase + row)*512 + k0 + seg*8;
            cp16(so + 18432 + row*144 + seg*16, g_W2th + gb);
            cp16(so + 27648 + row*144 + seg*16, g_W2tl + gb);
        }
    };

    prefetch(0); CP_COMMIT();

    float Xc[4][4] = {};

    for (int t = 0; t < 8; t++) {
        CP_WAIT0();
        __syncthreads();
        if (t + 1 < 8) { prefetch(t + 1); CP_COMMIT(); }
        uint32_t so = smb + (uint32_t)(t & 1) * G2STG;

        uint32_t ah[4][4], al[4][4];
        #pragma unroll
        for (int ks = 0; ks < 4; ks++) {
            uint32_t ad = so + (uint32_t)(16*wm + r8 + (q & 1)*8)*144 + ks*32 + (q >> 1)*16;
            ldm4(ah[ks], ad);
            ldm4(al[ks], ad + 9216);
        }
        #pragma unroll
        for (int nbp = 0; nbp < 2; nbp++) {
            #pragma unroll
            for (int ks = 0; ks < 4; ks++) {
                uint32_t ad = so + 18432
                            + (uint32_t)(wn*32 + nbp*16 + r8 + (q >> 1)*8)*144 + ks*32 + (q & 1)*16;
                uint32_t bh4[4], bl4[4];
                ldm4(bh4, ad);
                ldm4(bl4, ad + 9216);
                mma16816(Xc[2*nbp],   ah[ks], bh4);
                mma16816(Xc[2*nbp+1], ah[ks], bh4+2);
                mma16816(Xc[2*nbp],   ah[ks], bl4);
                mma16816(Xc[2*nbp+1], ah[ks], bl4+2);
                mma16816(Xc[2*nbp],   al[ks], bh4);
                mma16816(Xc[2*nbp+1], al[ks], bh4+2);
            }
        }
    }

    #pragma unroll
    for (int nf = 0; nf < 4; nf++) {
        #pragma unroll
        for (int e = 0; e < 4; e++) {
            int m = mBase + 16*wm + (e >> 1)*8 + (lane >> 2);
            int c = nBase + wn*32 + nf*8 + (lane & 3)*2 + (e & 1);
            outp[((size_t)m*DIMM + (c & 255))*2 + (c >> 8)] = Xc[nf][e];
        }
    }
}

// ---------------- HMMA attention (QK 2-pass, 3-stage pipeline) -------------------
#define SLOT 29696
#define SM_TOTAL (3*SLOT)

__global__ void __launch_bounds__(128, 2) attn_mma() {
    extern __shared__ __align__(16) unsigned char sm[];
    const int tid = threadIdx.x, w = tid >> 5, lane = tid & 31;
    const int bh = blockIdx.x;
    const int row0 = blockIdx.y * 32;
    const uint32_t smb = smem_u32(sm);
    const int r8 = lane & 7, q = lane >> 3;

    auto prefetch = [&](int t) {
        int ct = t * 64;
        uint32_t so = smb + (uint32_t)(t % 3) * SLOT;
        #pragma unroll
        for (int i = 0; i < 4; i++) {
            int c = tid + (i << 7);
            int row = c >> 2, pc = c & 3;
            size_t soff = ((size_t)bh*2048 + ct + (row & 63))*32 + pc*8;
            const __half* sh = (row < 64) ? g_Krh : g_Kih;
            const __half* sl = (row < 64) ? g_Krl : g_Kil;
            cp16(so + row*80 + pc*16, sh + soff);
            cp16(so + 10240 + row*80 + pc*16, sl + soff);
        }
        #pragma unroll
        for (int i = 0; i < 4; i++) {
            int c = tid + (i << 7);
            int dd = c >> 3, pc = c & 7;
            cp16(so + 20480 + dd*144 + pc*16,
                 g_VTh + ((size_t)bh*64 + dd)*2048 + ct + pc*8);
        }
    };

    prefetch(0); CP_COMMIT();
    prefetch(1); CP_COMMIT();

    const __half* Qh = (w < 2) ? g_Qrh : g_Qih;
    size_t qoff = ((size_t)bh*2048 + row0 + (w & 1)*16 + (lane >> 2))*32 + (lane & 3)*2;
    uint32_t aqh[2][4];
    #pragma unroll
    for (int ks = 0; ks < 2; ks++) {
        aqh[ks][0] = *(const uint32_t*)(Qh + qoff + ks*16);
        aqh[ks][1] = *(const uint32_t*)(Qh + qoff + 256 + ks*16);
        aqh[ks][2] = *(const uint32_t*)(Qh + qoff + ks*16 + 8);
        aqh[ks][3] = *(const uint32_t*)(Qh + qoff + 256 + ks*16 + 8);
    }

    float X[8][4] = {};
    float Y[8][4] = {};
    float l00 = 0.f, l01 = 0.f, l10 = 0.f, l11 = 0.f;
    const float C = (float)(1.4426950408889634 / 5.656854249492380);
    const float SHIFT = 10.0f;

    for (int t = 0; t < 32; t++) {
        if (t < 31) CP_WAIT1(); else CP_WAIT0();
        __syncthreads();
        if (t + 2 < 32) { prefetch(t + 2); CP_COMMIT(); }
        uint32_t so = smb + (uint32_t)(t % 3) * SLOT;

        float S[16][4];
        #pragma unroll
        for (int nb = 0; nb < 16; nb++)
            #pragma unroll
            for (int e = 0; e < 4; e++) S[nb][e] = 0.f;

        #pragma unroll
        for (int nbp = 0; nbp < 8; nbp++) {
            #pragma unroll
            for (int ks = 0; ks < 2; ks++) {
                uint32_t ad = so + (uint32_t)(nbp*16 + r8 + (q >> 1)*8)*80 + ks*32 + (q & 1)*16;
                uint32_t bh4[4], bl4[4];
                ldm4(bh4, ad);
                ldm4(bl4, ad + 10240);
                mma16816(S[2*nbp],   aqh[ks], bh4);
                mma16816(S[2*nbp+1], aqh[ks], bh4+2);
                mma16816(S[2*nbp],   aqh[ks], bl4);
                mma16816(S[2*nbp+1], aqh[ks], bl4+2);
            }
        }

        uint32_t vt = so + 20480;
        #pragma unroll
        for (int h2 = 0; h2 < 2; h2++) {
            uint32_t Pf[4][4];
            float ls0 = 0.f, ls1 = 0.f;
            #pragma unroll
            for (int ks = 0; ks < 4; ks++) {
                int nb = 8*h2 + 2*ks;
                float p00 = ex2(fmaf(S[nb][0],   C, -SHIFT));
                float p01 = ex2(fmaf(S[nb][1],   C, -SHIFT));
                float p02 = ex2(fmaf(S[nb][2],   C, -SHIFT));
                float p03 = ex2(fmaf(S[nb][3],   C, -SHIFT));
                float p10 = ex2(fmaf(S[nb+1][0], C, -SHIFT));
                float p11 = ex2(fmaf(S[nb+1][1], C, -SHIFT));
                float p12 = ex2(fmaf(S[nb+1][2], C, -SHIFT));
                float p13 = ex2(fmaf(S[nb+1][3], C, -SHIFT));
                ls0 += p00 + p01 + p10 + p11;
                ls1 += p02 + p03 + p12 + p13;
                Pf[ks][0] = pk(p00, p01);
                Pf[ks][1] = pk(p02, p03);
                Pf[ks][2] = pk(p10, p11);
                Pf[ks][3] = pk(p12, p13);
            }
            if (h2 == 0) { l00 += ls0; l10 += ls1; }
            else         { l01 += ls0; l11 += ls1; }

            float (*Z)[4] = h2 ? Y : X;
            #pragma unroll
            for (int dbp = 0; dbp < 4; dbp++) {
                #pragma unroll
                for (int ks = 0; ks < 4; ks++) {
                    uint32_t ad = vt + (uint32_t)(dbp*16 + r8 + (q >> 1)*8)*144 + ks*32 + (q & 1)*16;
                    uint32_t bv[4];
                    ldm4(bv, ad);
                    mma16816(Z[2*dbp],   Pf[ks], bv);
                    mma16816(Z[2*dbp+1], Pf[ks], bv+2);
                }
            }
        }
    }
    __syncthreads();

    l00 += __shfl_xor_sync(~0u, l00, 1); l00 += __shfl_xor_sync(~0u, l00, 2);
    l01 += __shfl_xor_sync(~0u, l01, 1); l01 += __shfl_xor_sync(~0u, l01, 2);
    l10 += __shfl_xor_sync(~0u, l10, 1); l10 += __shfl_xor_sync(~0u, l10, 2);
    l11 += __shfl_xor_sync(~0u, l11, 1); l11 += __shfl_xor_sync(~0u, l11, 2);
    float rl[2][2] = {{1.f/l00, 1.f/l01}, {1.f/l10, 1.f/l11}};

    float* orS = (float*)sm;             // [2][32][32]
    float* oiS = (float*)(sm + 8192);
    int grp = w >> 1;
    int mb = 16*(w & 1) + (lane >> 2);
    int dq = 2*(lane & 3);
    #pragma unroll
    for (int db = 0; db < 4; db++) {
        #pragma unroll
        for (int rr = 0; rr < 2; rr++) {
            #pragma unroll
            for (int dd = 0; dd < 2; dd++) {
                float x  = X[db][2*rr+dd]   * rl[rr][0];
                float x2 = X[db+4][2*rr+dd] * rl[rr][0];
                float y  = Y[db][2*rr+dd]   * rl[rr][1];
                float y2 = Y[db+4][2*rr+dd] * rl[rr][1];
                float orv = grp ? (-x2 - y) : (x - y2);
                float oiv = grp ? (x - y2)  : (x2 + y);
                int m = mb + rr*8, dcol = 8*db + dq + dd;
                orS[grp*1024 + m*32 + dcol] = orv;
                oiS[grp*1024 + m*32 + dcol] = oiv;
            }
        }
    }
    __syncthreads();
    {
        int b = bh >> 3, hh = bh & 7;
        for (int e = tid; e < 1024; e += 128) {
            int m = e >> 5, dcol = e & 31;
            float r  = orS[m*32 + dcol] + orS[1024 + m*32 + dcol];
            float im = oiS[m*32 + dcol] + oiS[1024 + m*32 + dcol];
            size_t o = ((size_t)(b*2048 + row0 + m))*512 + hh*32 + dcol;
            __half rh = __float2half_rn(r);
            __half ih = __float2half_rn(im);
            g_Mh[o]       = rh;
            g_Ml[o]       = __float2half_rn(r - __half2float(rh));
            g_Mh[o + 256] = ih;
            g_Ml[o + 256] = __float2half_rn(im - __half2float(ih));
        }
    }
}

// ---------------- launch -------------------------------------------------------------
extern "C" void kernel_launch(void* const* d_in, const int* in_sizes, int n_in,
                              void* d_out, int out_size) {
    const float* xr    = (const float*)d_in[0];
    const float* xi    = (const float*)d_in[1];
    const float* wq_r  = (const float*)d_in[2];
    const float* wq_i  = (const float*)d_in[3];
    const float* wkv_r = (const float*)d_in[4];
    const float* wkv_i = (const float*)d_in[5];
    const float* wo_r  = (const float*)d_in[6];
    const float* wo_i  = (const float*)d_in[7];
    float* out = (float*)d_out;

    cudaFuncSetAttribute(attn_mma,  cudaFuncAttributeMaxDynamicSharedMemorySize, SM_TOTAL);
    cudaFuncSetAttribute(gemm1_mma, cudaFuncAttributeMaxDynamicSharedMemorySize, G1SM);
    cudaFuncSetAttribute(gemm2_mma, cudaFuncAttributeMaxDynamicSharedMemorySize, G2SM);

    pack_all<<<(PK_TOT + 255)/256, 256>>>(xr, xi, wq_r, wq_i, wkv_r, wkv_i, wo_r, wo_i);
    gemm1_mma<<<dim3(NN1/64, M_TOT/64), 256, G1SM>>>();
    attn_mma<<<dim3(16, 64), 128, SM_TOTAL>>>();
    gemm2_mma<<<dim3(NN2/64, M_TOT/64), 256, G2SM>>>(out);
}